// round 3
// baseline (speedup 1.0000x reference)
#include <cuda_runtime.h>
#include <math.h>

#define BATCH   2
#define SEQ     2048
#define CMODEL  512
#define NHEADS  8
#define DK      64
#define DFF     2048
#define QKVC    1536
#define NTOK    (BATCH*SEQ)     /* 4096 */
#define NTOP    512
#define SCALE   0.125f
#define LNEPS   1e-5f
#define NEGINF  -3.402823466e38f

typedef unsigned long long u64;

// ---------------- f32x2 packed helpers (sm_103a FFMA2 path) ----------------
__device__ __forceinline__ u64 fdup(float x) {
    u64 r; unsigned xi = __float_as_uint(x);
    asm("mov.b64 %0, {%1, %1};" : "=l"(r) : "r"(xi));
    return r;
}
__device__ __forceinline__ u64 ffma2(u64 a, u64 b, u64 c) {
    u64 d;
    asm("fma.rn.f32x2 %0, %1, %2, %3;" : "=l"(d) : "l"(a), "l"(b), "l"(c));
    return d;
}
__device__ __forceinline__ float2 unpk(u64 v) {
    unsigned lo, hi;
    asm("mov.b64 {%0, %1}, %2;" : "=r"(lo), "=r"(hi) : "l"(v));
    return make_float2(__uint_as_float(lo), __uint_as_float(hi));
}

// ---------------- scratch (static device globals; no allocation) ----------------
__device__ float g_qkv[NTOK*QKVC];          // qkv activations; later reused as packed conv input
__device__ float g_hff[NTOK*DFF];           // FFN hidden
__device__ float g_attnO[NTOK*CMODEL];      // attention output (pre-projection)
__device__ float g_t1[NTOK*CMODEL];         // generic [NTOK,C] temp
__device__ float g_x1[NTOK*CMODEL];         // after LN1
__device__ float g_x2[NTOK*CMODEL];         // after LN2
__device__ float g_cy[NTOK*CMODEL];         // conv output (pre-pool)
__device__ float g_wr[3*CMODEL*CMODEL];     // repacked conv weight [3*C, C]
__device__ float g_rowmax[BATCH*NHEADS*SEQ];
__device__ float g_M[BATCH*NHEADS*SEQ];
__device__ float g_ksum[BATCH*NHEADS*DK];
__device__ float g_vmean[BATCH*NHEADS*DK];
__device__ int   g_topidx[BATCH*NHEADS*NTOP];

// ---------------- tiled SGEMM with FFMA2: C[M,N] = A[M,K] @ B[K,N] + bias, opt GELU ----------------
__global__ __launch_bounds__(256) void k_sgemm(
    const float* __restrict__ A, const float* __restrict__ B,
    const float* __restrict__ bias, float* __restrict__ C,
    int M, int N, int K, int gelu)
{
    __shared__ u64   As2[16][128];   // A tile, k-major, values pre-duplicated
    __shared__ float Bs[16][128];
    const int bm = blockIdx.y * 128;
    const int bn = blockIdx.x * 128;
    const int t  = threadIdx.x;
    const int tx = t & 15, ty = t >> 4;
    const int arow = t >> 1, acol = (t & 1) * 8;
    const int brow = t >> 4, bcol = (t & 15) * 8;

    u64 acc[8][4];
#pragma unroll
    for (int i = 0; i < 8; i++)
#pragma unroll
        for (int j = 0; j < 4; j++) acc[i][j] = 0ull;

    const float* Ap = A + (size_t)(bm + arow) * K + acol;
    const float* Bp = B + (size_t)brow * N + bn + bcol;

    for (int k0 = 0; k0 < K; k0 += 16) {
        float4 a0 = *(const float4*)(Ap + k0);
        float4 a1 = *(const float4*)(Ap + k0 + 4);
        float4 b0 = *(const float4*)(Bp + (size_t)k0 * N);
        float4 b1 = *(const float4*)(Bp + (size_t)k0 * N + 4);
        As2[acol + 0][arow] = fdup(a0.x); As2[acol + 1][arow] = fdup(a0.y);
        As2[acol + 2][arow] = fdup(a0.z); As2[acol + 3][arow] = fdup(a0.w);
        As2[acol + 4][arow] = fdup(a1.x); As2[acol + 5][arow] = fdup(a1.y);
        As2[acol + 6][arow] = fdup(a1.z); As2[acol + 7][arow] = fdup(a1.w);
        *(float4*)&Bs[brow][bcol]     = b0;
        *(float4*)&Bs[brow][bcol + 4] = b1;
        __syncthreads();
#pragma unroll
        for (int kk = 0; kk < 16; kk++) {
            ulonglong2 aA = *(const ulonglong2*)&As2[kk][ty * 8];
            ulonglong2 aB = *(const ulonglong2*)&As2[kk][ty * 8 + 2];
            ulonglong2 aC = *(const ulonglong2*)&As2[kk][ty * 8 + 4];
            ulonglong2 aD = *(const ulonglong2*)&As2[kk][ty * 8 + 6];
            ulonglong2 b01 = *(const ulonglong2*)&Bs[kk][tx * 8];
            ulonglong2 b23 = *(const ulonglong2*)&Bs[kk][tx * 8 + 4];
            u64 az[8] = {aA.x, aA.y, aB.x, aB.y, aC.x, aC.y, aD.x, aD.y};
            u64 bz[4] = {b01.x, b01.y, b23.x, b23.y};
#pragma unroll
            for (int i = 0; i < 8; i++)
#pragma unroll
                for (int j = 0; j < 4; j++) acc[i][j] = ffma2(az[i], bz[j], acc[i][j]);
        }
        __syncthreads();
    }

#pragma unroll
    for (int i = 0; i < 8; i++) {
        const int row = bm + ty * 8 + i;
        float* Cp = C + (size_t)row * N + bn + tx * 8;
#pragma unroll
        for (int j = 0; j < 4; j++) {
            float2 v = unpk(acc[i][j]);
            float v0 = v.x + bias[bn + tx * 8 + 2 * j];
            float v1 = v.y + bias[bn + tx * 8 + 2 * j + 1];
            if (gelu) {
                v0 = 0.5f * v0 * (1.0f + erff(v0 * 0.70710678118654752f));
                v1 = 0.5f * v1 * (1.0f + erff(v1 * 0.70710678118654752f));
            }
            Cp[2 * j]     = v0;
            Cp[2 * j + 1] = v1;
        }
    }
}

// ---------------- per-(b,h) ksum / vmean ----------------
__global__ __launch_bounds__(256) void k_kstats()
{
    const int bh = blockIdx.x, b = bh >> 3, h = bh & 7;
    const int t = threadIdx.x;
    const int d = t & 63, c = t >> 6;    // 4 chunks of 512 rows
    float ks = 0.f, vs = 0.f;
    for (int n = c * 512; n < (c + 1) * 512; n++) {
        const float* p = g_qkv + (size_t)(b * SEQ + n) * QKVC + CMODEL + h * DK + d;
        ks += p[0];
        vs += p[CMODEL];
    }
    __shared__ float sk[256], sv[256];
    sk[t] = ks; sv[t] = vs;
    __syncthreads();
    if (t < 64) {
        float a = sk[t] + sk[t + 64] + sk[t + 128] + sk[t + 192];
        float v = sv[t] + sv[t + 64] + sv[t + 128] + sv[t + 192];
        g_ksum[bh * DK + t]  = a;
        g_vmean[bh * DK + t] = v * (1.0f / SEQ);
    }
}

// ---------------- streamed QK^T row-max + M with FFMA2 (no score storage) ----------------
__global__ __launch_bounds__(256) void k_rowmax()
{
    const int bh = blockIdx.y, b = bh >> 3, h = bh & 7;
    const int bm = blockIdx.x * 128;
    const int t = threadIdx.x;
    const int tx = t & 15, ty = t >> 4;

    __shared__ u64   Qs2[16][128];
    __shared__ float Ks[16][128];
    __shared__ float red[128][17];
    __shared__ float ks[64];
    if (t < 64) ks[t] = g_ksum[bh * DK + t];

    float lmax[8];
#pragma unroll
    for (int i = 0; i < 8; i++) lmax[i] = NEGINF;

    const int arow = t >> 1, acol = (t & 1) * 8;
    const float* qbase = g_qkv + (size_t)(b * SEQ) * QKVC + h * DK;
    const float* kbase = qbase + CMODEL;

    for (int m0 = 0; m0 < SEQ; m0 += 128) {
        u64 acc[8][4];
#pragma unroll
        for (int i = 0; i < 8; i++)
#pragma unroll
            for (int j = 0; j < 4; j++) acc[i][j] = 0ull;

        for (int k0 = 0; k0 < DK; k0 += 16) {
            float4 a0 = *(const float4*)(qbase + (size_t)(bm + arow) * QKVC + k0 + acol);
            float4 a1 = *(const float4*)(qbase + (size_t)(bm + arow) * QKVC + k0 + acol + 4);
            float4 b0 = *(const float4*)(kbase + (size_t)(m0 + arow) * QKVC + k0 + acol);
            float4 b1 = *(const float4*)(kbase + (size_t)(m0 + arow) * QKVC + k0 + acol + 4);
            Qs2[acol + 0][arow] = fdup(a0.x); Qs2[acol + 1][arow] = fdup(a0.y);
            Qs2[acol + 2][arow] = fdup(a0.z); Qs2[acol + 3][arow] = fdup(a0.w);
            Qs2[acol + 4][arow] = fdup(a1.x); Qs2[acol + 5][arow] = fdup(a1.y);
            Qs2[acol + 6][arow] = fdup(a1.z); Qs2[acol + 7][arow] = fdup(a1.w);
            Ks[acol + 0][arow] = b0.x; Ks[acol + 1][arow] = b0.y;
            Ks[acol + 2][arow] = b0.z; Ks[acol + 3][arow] = b0.w;
            Ks[acol + 4][arow] = b1.x; Ks[acol + 5][arow] = b1.y;
            Ks[acol + 6][arow] = b1.z; Ks[acol + 7][arow] = b1.w;
            __syncthreads();
#pragma unroll
            for (int kk = 0; kk < 16; kk++) {
                ulonglong2 aA = *(const ulonglong2*)&Qs2[kk][ty * 8];
                ulonglong2 aB = *(const ulonglong2*)&Qs2[kk][ty * 8 + 2];
                ulonglong2 aC = *(const ulonglong2*)&Qs2[kk][ty * 8 + 4];
                ulonglong2 aD = *(const ulonglong2*)&Qs2[kk][ty * 8 + 6];
                ulonglong2 b01 = *(const ulonglong2*)&Ks[kk][tx * 8];
                ulonglong2 b23 = *(const ulonglong2*)&Ks[kk][tx * 8 + 4];
                u64 az[8] = {aA.x, aA.y, aB.x, aB.y, aC.x, aC.y, aD.x, aD.y};
                u64 bz[4] = {b01.x, b01.y, b23.x, b23.y};
#pragma unroll
                for (int i = 0; i < 8; i++)
#pragma unroll
                    for (int j = 0; j < 4; j++) acc[i][j] = ffma2(az[i], bz[j], acc[i][j]);
            }
            __syncthreads();
        }
#pragma unroll
        for (int i = 0; i < 8; i++) {
            float mx = lmax[i];
#pragma unroll
            for (int j = 0; j < 4; j++) {
                float2 v = unpk(acc[i][j]);
                mx = fmaxf(mx, fmaxf(v.x, v.y));
            }
            lmax[i] = mx;
        }
    }

#pragma unroll
    for (int i = 0; i < 8; i++) red[ty * 8 + i][tx] = lmax[i];
    __syncthreads();
    if (t < 128) {
        float mx = red[t][0];
#pragma unroll
        for (int j = 1; j < 16; j++) mx = fmaxf(mx, red[t][j]);
        float qd = 0.f;
        const float* qp = qbase + (size_t)(bm + t) * QKVC;
#pragma unroll 8
        for (int d = 0; d < 64; d++) qd += qp[d] * ks[d];
        g_rowmax[bh * SEQ + bm + t] = SCALE * mx;
        g_M[bh * SEQ + bm + t]      = SCALE * mx - SCALE * qd * (1.0f / SEQ);
    }
}

// ---------------- exact top-512 per (b,h): in-smem bitonic sort (jax tie-break) ----------------
__global__ __launch_bounds__(1024) void k_topk()
{
    const int bh = blockIdx.x;
    const int t = threadIdx.x;
    __shared__ float sv[2048];
    __shared__ int   si[2048];
    sv[t]        = g_M[bh * SEQ + t];        si[t]        = t;
    sv[t + 1024] = g_M[bh * SEQ + t + 1024]; si[t + 1024] = t + 1024;

    for (int k = 2; k <= 2048; k <<= 1) {
        for (int j = k >> 1; j > 0; j >>= 1) {
            __syncthreads();
#pragma unroll 1
            for (int e = t; e < 2048; e += 1024) {
                const int p = e ^ j;
                if (p > e) {
                    float va = sv[e], vb = sv[p];
                    int   ia = si[e], ib = si[p];
                    bool gtr = (va > vb) || (va == vb && ia < ib);
                    bool desc = ((e & k) == 0);
                    if (desc ? !gtr : gtr) {
                        sv[e] = vb; sv[p] = va;
                        si[e] = ib; si[p] = ia;
                    }
                }
            }
        }
    }
    __syncthreads();
    if (t < NTOP) g_topidx[bh * NTOP + t] = si[t];
}

// ---------------- fill all rows with vmean (unselected rows keep this) ----------------
__global__ __launch_bounds__(256) void k_fill()
{
    const int i = blockIdx.x * 256 + threadIdx.x;
    const int c = i & 511;
    const int tok = i >> 9;
    const int b = tok >> 11;
    g_attnO[i] = g_vmean[(b * NHEADS + (c >> 6)) * DK + (c & 63)];
}

// ---------------- softmax @ V for selected rows (row max known -> single pass) ----------------
__global__ __launch_bounds__(128) void k_attn_sel()
{
    const int bh = blockIdx.y, b = bh >> 3, h = bh & 7;
    const int t = threadIdx.x;

    __shared__ float Qs[16][65];
    __shared__ float Ks[64][65];
    __shared__ float Vs[64][65];
    __shared__ float Se[16][64];
    __shared__ float sume[16];
    __shared__ float rmax[16];
    __shared__ int   nidx[16];

    if (t < 16) {
        int n = g_topidx[bh * NTOP + blockIdx.x * 16 + t];
        nidx[t] = n;
        sume[t] = 0.f;
        rmax[t] = g_rowmax[bh * SEQ + n];
    }
    __syncthreads();

    const int r  = t >> 3;
    const int mg = (t & 7) * 8;
    const int dg = (t & 7) * 8;

    {
        const int qr = t >> 3, c0 = (t & 7) * 8;
        const float* qp = g_qkv + (size_t)(b * SEQ + nidx[qr]) * QKVC + h * DK + c0;
        float4 q0 = *(const float4*)qp, q1 = *(const float4*)(qp + 4);
        Qs[qr][c0 + 0] = q0.x; Qs[qr][c0 + 1] = q0.y; Qs[qr][c0 + 2] = q0.z; Qs[qr][c0 + 3] = q0.w;
        Qs[qr][c0 + 4] = q1.x; Qs[qr][c0 + 5] = q1.y; Qs[qr][c0 + 6] = q1.z; Qs[qr][c0 + 7] = q1.w;
    }
    const float rm = rmax[r];

    float o[8];
#pragma unroll
    for (int i = 0; i < 8; i++) o[i] = 0.f;

    for (int m0 = 0; m0 < SEQ; m0 += 64) {
        __syncthreads();
        for (int f = t; f < 1024; f += 128) {
            const int mr = f >> 4, c4 = (f & 15) * 4;
            const float* kp = g_qkv + (size_t)(b * SEQ + m0 + mr) * QKVC + CMODEL + h * DK + c4;
            float4 kv = *(const float4*)kp;
            float4 vv = *(const float4*)(kp + CMODEL);
            Ks[mr][c4 + 0] = kv.x; Ks[mr][c4 + 1] = kv.y; Ks[mr][c4 + 2] = kv.z; Ks[mr][c4 + 3] = kv.w;
            Vs[mr][c4 + 0] = vv.x; Vs[mr][c4 + 1] = vv.y; Vs[mr][c4 + 2] = vv.z; Vs[mr][c4 + 3] = vv.w;
        }
        __syncthreads();

        float s[8];
#pragma unroll
        for (int jj = 0; jj < 8; jj++) s[jj] = 0.f;
#pragma unroll 8
        for (int d = 0; d < 64; d++) {
            const float qv = Qs[r][d];
#pragma unroll
            for (int jj = 0; jj < 8; jj++) s[jj] += qv * Ks[mg + jj][d];
        }
        float lsum = 0.f;
#pragma unroll
        for (int jj = 0; jj < 8; jj++) {
            float ev = __expf(s[jj] * SCALE - rm);
            Se[r][mg + jj] = ev;
            lsum += ev;
        }
        atomicAdd(&sume[r], lsum);
        __syncthreads();

#pragma unroll 8
        for (int m = 0; m < 64; m++) {
            const float ev = Se[r][m];
#pragma unroll
            for (int i = 0; i < 8; i++) o[i] += ev * Vs[m][dg + i];
        }
    }
    __syncthreads();
    const float inv = 1.0f / sume[r];
    float* op = g_attnO + (size_t)(b * SEQ + nidx[r]) * CMODEL + h * DK + dg;
#pragma unroll
    for (int i = 0; i < 8; i++) op[i] = o[i] * inv;
}

// ---------------- fused residual add + LayerNorm over C=512 ----------------
__global__ __launch_bounds__(128) void k_addln(
    const float* __restrict__ A, const float* __restrict__ Bv,
    const float* __restrict__ g, const float* __restrict__ be, float* __restrict__ O)
{
    const int row = blockIdx.x, t = threadIdx.x;
    float4 a = ((const float4*)(A  + (size_t)row * CMODEL))[t];
    float4 b = ((const float4*)(Bv + (size_t)row * CMODEL))[t];
    float v0 = a.x + b.x, v1 = a.y + b.y, v2 = a.z + b.z, v3 = a.w + b.w;

    __shared__ float ws[4];
    float s = v0 + v1 + v2 + v3;
#pragma unroll
    for (int o = 16; o > 0; o >>= 1) s += __shfl_xor_sync(0xffffffffu, s, o);
    if ((t & 31) == 0) ws[t >> 5] = s;
    __syncthreads();
    const float mean = (ws[0] + ws[1] + ws[2] + ws[3]) * (1.0f / CMODEL);
    v0 -= mean; v1 -= mean; v2 -= mean; v3 -= mean;
    float q = v0 * v0 + v1 * v1 + v2 * v2 + v3 * v3;
#pragma unroll
    for (int o = 16; o > 0; o >>= 1) q += __shfl_xor_sync(0xffffffffu, q, o);
    __syncthreads();
    if ((t & 31) == 0) ws[t >> 5] = q;
    __syncthreads();
    const float var = (ws[0] + ws[1] + ws[2] + ws[3]) * (1.0f / CMODEL);
    const float rs = rsqrtf(var + LNEPS);
    float4 gg = ((const float4*)g)[t], bb = ((const float4*)be)[t];
    float4 out;
    out.x = v0 * rs * gg.x + bb.x;
    out.y = v1 * rs * gg.y + bb.y;
    out.z = v2 * rs * gg.z + bb.z;
    out.w = v3 * rs * gg.w + bb.w;
    ((float4*)(O + (size_t)row * CMODEL))[t] = out;
}

// ---------------- conv weight repack: wr[k*C+ci, co] = conv_w[co, ci, k] ----------------
__global__ __launch_bounds__(256) void k_packW(const float* __restrict__ conv_w)
{
    const int i = blockIdx.x * 256 + threadIdx.x;
    const int co = i & 511;
    const int rr = i >> 9;
    const int ci = rr & 511;
    const int k  = rr >> 9;
    g_wr[i] = conv_w[(co * CMODEL + ci) * 3 + k];
}

// ---------------- gather circular-shifted x2 into packed conv input (reuses g_qkv) ----------------
__global__ __launch_bounds__(256) void k_packX()
{
    const int i = blockIdx.x * 256 + threadIdx.x;
    const int col = i % QKVC;
    const int tok = i / QKVC;
    const int b = tok >> 11, n = tok & 2047;
    const int k = col >> 9, ci = col & 511;
    const int ns = (n - 1 + k + SEQ) & (SEQ - 1);    // circular
    g_qkv[i] = g_x2[(size_t)(b * SEQ + ns) * CMODEL + ci];
}

// ---------------- maxpool(k3,s2,p1) + ELU + LayerNorm -> final output ----------------
__global__ __launch_bounds__(128) void k_poolln(
    const float* __restrict__ Y, const float* __restrict__ g,
    const float* __restrict__ be, float* __restrict__ O)
{
    const int row = blockIdx.x;           // b*1024 + j
    const int b = row >> 10, j = row & 1023;
    const int t = threadIdx.x;
    const int c = t * 4;

    float m0 = NEGINF, m1 = NEGINF, m2 = NEGINF, m3 = NEGINF;
#pragma unroll
    for (int dn = 0; dn < 3; dn++) {
        const int n = 2 * j - 1 + dn;
        if (n >= 0 && n < SEQ) {
            float4 w = *(const float4*)(Y + (size_t)(b * SEQ + n) * CMODEL + c);
            m0 = fmaxf(m0, w.x); m1 = fmaxf(m1, w.y);
            m2 = fmaxf(m2, w.z); m3 = fmaxf(m3, w.w);
        }
    }
    float v0 = m0 > 0.f ? m0 : expm1f(m0);
    float v1 = m1 > 0.f ? m1 : expm1f(m1);
    float v2 = m2 > 0.f ? m2 : expm1f(m2);
    float v3 = m3 > 0.f ? m3 : expm1f(m3);

    __shared__ float ws[4];
    float s = v0 + v1 + v2 + v3;
#pragma unroll
    for (int o = 16; o > 0; o >>= 1) s += __shfl_xor_sync(0xffffffffu, s, o);
    if ((t & 31) == 0) ws[t >> 5] = s;
    __syncthreads();
    const float mean = (ws[0] + ws[1] + ws[2] + ws[3]) * (1.0f / CMODEL);
    v0 -= mean; v1 -= mean; v2 -= mean; v3 -= mean;
    float q = v0 * v0 + v1 * v1 + v2 * v2 + v3 * v3;
#pragma unroll
    for (int o = 16; o > 0; o >>= 1) q += __shfl_xor_sync(0xffffffffu, q, o);
    __syncthreads();
    if ((t & 31) == 0) ws[t >> 5] = q;
    __syncthreads();
    const float var = (ws[0] + ws[1] + ws[2] + ws[3]) * (1.0f / CMODEL);
    const float rs = rsqrtf(var + LNEPS);
    float4 gg = ((const float4*)g)[t], bb = ((const float4*)be)[t];
    float4 out;
    out.x = v0 * rs * gg.x + bb.x;
    out.y = v1 * rs * gg.y + bb.y;
    out.z = v2 * rs * gg.z + bb.z;
    out.w = v3 * rs * gg.w + bb.w;
    ((float4*)(O + (size_t)row * CMODEL))[t] = out;
}

// ---------------- host orchestration ----------------
extern "C" void kernel_launch(void* const* d_in, const int* in_sizes, int n_in,
                              void* d_out, int out_size)
{
    (void)in_sizes; (void)n_in; (void)out_size;
    const float* x      = (const float*)d_in[0];
    const float* qkv_w  = (const float*)d_in[1];
    const float* qkv_b  = (const float*)d_in[2];
    const float* out_w  = (const float*)d_in[3];
    const float* out_b  = (const float*)d_in[4];
    const float* ffn_w1 = (const float*)d_in[5];
    const float* ffn_b1 = (const float*)d_in[6];
    const float* ffn_w2 = (const float*)d_in[7];
    const float* ffn_b2 = (const float*)d_in[8];
    const float* n1_g   = (const float*)d_in[9];
    const float* n1_b   = (const float*)d_in[10];
    const float* n2_g   = (const float*)d_in[11];
    const float* n2_b   = (const float*)d_in[12];
    const float* conv_w = (const float*)d_in[13];
    const float* conv_b = (const float*)d_in[14];
    const float* cn_g   = (const float*)d_in[15];
    const float* cn_b   = (const float*)d_in[16];
    float* out = (float*)d_out;

    float *p_qkv, *p_hff, *p_attnO, *p_t1, *p_x1, *p_x2, *p_cy, *p_wr;
    cudaGetSymbolAddress((void**)&p_qkv,   g_qkv);
    cudaGetSymbolAddress((void**)&p_hff,   g_hff);
    cudaGetSymbolAddress((void**)&p_attnO, g_attnO);
    cudaGetSymbolAddress((void**)&p_t1,    g_t1);
    cudaGetSymbolAddress((void**)&p_x1,    g_x1);
    cudaGetSymbolAddress((void**)&p_x2,    g_x2);
    cudaGetSymbolAddress((void**)&p_cy,    g_cy);
    cudaGetSymbolAddress((void**)&p_wr,    g_wr);

    // 1) QKV projection
    k_sgemm<<<dim3(QKVC / 128, NTOK / 128), 256>>>(x, qkv_w, qkv_b, p_qkv, NTOK, QKVC, CMODEL, 0);
    // 2) per-head key-sum / value-mean
    k_kstats<<<BATCH * NHEADS, 256>>>();
    // 3) streamed row-max of QK^T and sparsity measure M
    k_rowmax<<<dim3(SEQ / 128, BATCH * NHEADS), 256>>>();
    // 4) exact top-512 per head
    k_topk<<<BATCH * NHEADS, 1024>>>();
    // 5) default all rows to vmean (uniform-softmax result), then overwrite selected
    k_fill<<<(NTOK * CMODEL) / 256, 256>>>();
    k_attn_sel<<<dim3(NTOP / 16, BATCH * NHEADS), 128>>>();
    // 6) output projection + LN1
    k_sgemm<<<dim3(CMODEL / 128, NTOK / 128), 256>>>(p_attnO, out_w, out_b, p_t1, NTOK, CMODEL, CMODEL, 0);
    k_addln<<<NTOK, 128>>>(x, p_t1, n1_g, n1_b, p_x1);
    // 7) FFN + LN2
    k_sgemm<<<dim3(DFF / 128, NTOK / 128), 256>>>(p_x1, ffn_w1, ffn_b1, p_hff, NTOK, DFF, CMODEL, 1);
    k_sgemm<<<dim3(CMODEL / 128, NTOK / 128), 256>>>(p_hff, ffn_w2, ffn_b2, p_t1, NTOK, CMODEL, DFF, 0);
    k_addln<<<NTOK, 128>>>(p_x1, p_t1, n2_g, n2_b, p_x2);
    // 8) circular conv1d(k=3) as GEMM over packed input
    k_packW<<<(3 * CMODEL * CMODEL) / 256, 256>>>(conv_w);
    k_packX<<<(NTOK * QKVC) / 256, 256>>>();
    k_sgemm<<<dim3(CMODEL / 128, NTOK / 128), 256>>>(p_qkv, p_wr, conv_b, p_cy, NTOK, CMODEL, 3 * CMODEL, 0);
    // 9) maxpool + ELU + LN -> d_out
    k_poolln<<<BATCH * (SEQ / 2), 128>>>(p_cy, cn_g, cn_b, out);
}

// round 4
// speedup vs baseline: 1.3932x; 1.3932x over previous
#include <cuda_runtime.h>
#include <cuda_bf16.h>
#include <math.h>

#define BATCH   2
#define SEQ     2048
#define CMODEL  512
#define NHEADS  8
#define DK      64
#define DFF     2048
#define QKVC    1536
#define NTOK    (BATCH*SEQ)     /* 4096 */
#define NTOP    512
#define SCALE   0.125f
#define LNEPS   1e-5f
#define NEGINF  -3.402823466e38f

// ---------------- scratch (static device globals; no allocation) ----------------
__device__ float g_qkv[NTOK*QKVC];          // qkv activations; later reused as packed conv input
__device__ float g_hff[NTOK*DFF];           // FFN hidden
__device__ float g_attnO[NTOK*CMODEL];      // attention output (pre-projection)
__device__ float g_t1[NTOK*CMODEL];         // generic [NTOK,C] temp
__device__ float g_x1[NTOK*CMODEL];         // after LN1
__device__ float g_x2[NTOK*CMODEL];         // after LN2
__device__ float g_cy[NTOK*CMODEL];         // conv output (pre-pool)
__device__ float g_wr[3*CMODEL*CMODEL];     // repacked conv weight [3*C, C]
__device__ float g_rowmax[BATCH*NHEADS*SEQ];
__device__ float g_M[BATCH*NHEADS*SEQ];
__device__ float g_ksum[BATCH*NHEADS*DK];
__device__ float g_vmean[BATCH*NHEADS*DK];
__device__ int   g_topidx[BATCH*NHEADS*NTOP];
// split-bf16 operand buffers
__device__ __nv_bfloat16 g_ah[NTOK*DFF];    // activation hi (max 4096x2048)
__device__ __nv_bfloat16 g_al[NTOK*DFF];    // activation lo
__device__ __nv_bfloat16 g_bh[DFF*CMODEL];  // weight hi (max 2048x512 / 512x2048)
__device__ __nv_bfloat16 g_bl[DFF*CMODEL];  // weight lo

// ---------------- fp32 -> (hi,lo) bf16 split ----------------
__global__ __launch_bounds__(256) void k_cvt(
    const float* __restrict__ s, __nv_bfloat16* __restrict__ hi,
    __nv_bfloat16* __restrict__ lo, int n)
{
    const int i = blockIdx.x * 256 + threadIdx.x;
    if (i < n) {
        float x = s[i];
        __nv_bfloat16 h = __float2bfloat16_rn(x);
        hi[i] = h;
        lo[i] = __float2bfloat16_rn(x - __bfloat162float(h));
    }
}

// ---------------- mma helpers ----------------
__device__ __forceinline__ void mma16816(float* c, const unsigned* a, const unsigned* b) {
    asm volatile(
        "mma.sync.aligned.m16n8k16.row.col.f32.bf16.bf16.f32 "
        "{%0,%1,%2,%3}, {%4,%5,%6,%7}, {%8,%9}, {%0,%1,%2,%3};"
        : "+f"(c[0]), "+f"(c[1]), "+f"(c[2]), "+f"(c[3])
        : "r"(a[0]), "r"(a[1]), "r"(a[2]), "r"(a[3]), "r"(b[0]), "r"(b[1]));
}
__device__ __forceinline__ void ldsm4(unsigned* r, const void* p) {
    unsigned addr = (unsigned)__cvta_generic_to_shared(p);
    asm volatile("ldmatrix.sync.aligned.m8n8.x4.shared.b16 {%0,%1,%2,%3}, [%4];"
                 : "=r"(r[0]), "=r"(r[1]), "=r"(r[2]), "=r"(r[3]) : "r"(addr));
}
__device__ __forceinline__ void ldsm4t(unsigned* r, const void* p) {
    unsigned addr = (unsigned)__cvta_generic_to_shared(p);
    asm volatile("ldmatrix.sync.aligned.m8n8.x4.trans.shared.b16 {%0,%1,%2,%3}, [%4];"
                 : "=r"(r[0]), "=r"(r[1]), "=r"(r[2]), "=r"(r[3]) : "r"(addr));
}

// ---------------- split-bf16 tensor-core GEMM: C = Ah@Bh + Ah@Bl + Al@Bh (+bias, opt GELU) ----------------
// A row-major [M,K] (hi/lo), B row-major [K,N] (hi/lo). BM=BN=128, BK=32, 256 thr.
#define APAD 40
#define BPAD 136
__global__ __launch_bounds__(256) void k_hgemm(
    const __nv_bfloat16* __restrict__ Agh, const __nv_bfloat16* __restrict__ Agl,
    const __nv_bfloat16* __restrict__ Bgh, const __nv_bfloat16* __restrict__ Bgl,
    const float* __restrict__ bias, float* __restrict__ C,
    int M, int N, int K, int gelu)
{
    __shared__ __align__(16) __nv_bfloat16 Ah[128][APAD];
    __shared__ __align__(16) __nv_bfloat16 Al[128][APAD];
    __shared__ __align__(16) __nv_bfloat16 Bh[32][BPAD];
    __shared__ __align__(16) __nv_bfloat16 Bl[32][BPAD];

    const int t = threadIdx.x;
    const int warp = t >> 5, lane = t & 31;
    const int wm = warp >> 1, wn = warp & 1;          // warp tile: rows wm*32, cols wn*64
    const int bm = blockIdx.y * 128, bn = blockIdx.x * 128;

    float acc[2][8][4];
#pragma unroll
    for (int i = 0; i < 2; i++)
#pragma unroll
        for (int j = 0; j < 8; j++)
#pragma unroll
            for (int q = 0; q < 4; q++) acc[i][j][q] = 0.f;

    // gmem->smem indices
    const int ar0 = t >> 2,  ac0 = (t & 3) * 8;        // A: 2 iters of (row, 8 cols)
    const int br0 = t >> 4,  bc0 = (t & 15) * 8;       // B: 2 iters

    for (int k0 = 0; k0 < K; k0 += 32) {
#pragma unroll
        for (int i = 0; i < 2; i++) {
            const int r = ar0 + i * 64;
            *(uint4*)&Ah[r][ac0] = *(const uint4*)(Agh + (size_t)(bm + r) * K + k0 + ac0);
            *(uint4*)&Al[r][ac0] = *(const uint4*)(Agl + (size_t)(bm + r) * K + k0 + ac0);
        }
#pragma unroll
        for (int i = 0; i < 2; i++) {
            const int r = br0 + i * 16;
            *(uint4*)&Bh[r][bc0] = *(const uint4*)(Bgh + (size_t)(k0 + r) * N + bn + bc0);
            *(uint4*)&Bl[r][bc0] = *(const uint4*)(Bgl + (size_t)(k0 + r) * N + bn + bc0);
        }
        __syncthreads();

#pragma unroll
        for (int ks = 0; ks < 32; ks += 16) {
            unsigned ah[2][4], al[2][4];
#pragma unroll
            for (int mt = 0; mt < 2; mt++) {
                const int r = wm * 32 + mt * 16 + (lane & 15);
                const int c = ks + (lane >> 4) * 8;
                ldsm4(ah[mt], &Ah[r][c]);
                ldsm4(al[mt], &Al[r][c]);
            }
#pragma unroll
            for (int np = 0; np < 4; np++) {
                unsigned bh[4], bl[4];
                const int r = ks + (lane & 15);
                const int c = wn * 64 + np * 16 + (lane >> 4) * 8;
                ldsm4t(bh, &Bh[r][c]);
                ldsm4t(bl, &Bl[r][c]);
#pragma unroll
                for (int mt = 0; mt < 2; mt++) {
                    mma16816(acc[mt][2 * np],     ah[mt], bh);
                    mma16816(acc[mt][2 * np],     ah[mt], bl);
                    mma16816(acc[mt][2 * np],     al[mt], bh);
                    mma16816(acc[mt][2 * np + 1], ah[mt], bh + 2);
                    mma16816(acc[mt][2 * np + 1], ah[mt], bl + 2);
                    mma16816(acc[mt][2 * np + 1], al[mt], bh + 2);
                }
            }
        }
        __syncthreads();
    }

    // epilogue
    const int g = lane >> 2, tg = lane & 3;
#pragma unroll
    for (int mt = 0; mt < 2; mt++) {
#pragma unroll
        for (int nt = 0; nt < 8; nt++) {
            const int col = bn + wn * 64 + nt * 8 + 2 * tg;
            const float b0 = bias[col], b1 = bias[col + 1];
#pragma unroll
            for (int hrow = 0; hrow < 2; hrow++) {
                const int row = bm + wm * 32 + mt * 16 + g + hrow * 8;
                float v0 = acc[mt][nt][2 * hrow]     + b0;
                float v1 = acc[mt][nt][2 * hrow + 1] + b1;
                if (gelu) {
                    v0 = 0.5f * v0 * (1.0f + erff(v0 * 0.70710678118654752f));
                    v1 = 0.5f * v1 * (1.0f + erff(v1 * 0.70710678118654752f));
                }
                float2 o = make_float2(v0, v1);
                *(float2*)(C + (size_t)row * N + col) = o;
            }
        }
    }
}

// ---------------- scalar fp32 SGEMM (R1 version; used for selection-critical QKV) ----------------
__global__ __launch_bounds__(256) void k_sgemm(
    const float* __restrict__ A, const float* __restrict__ B,
    const float* __restrict__ bias, float* __restrict__ C,
    int M, int N, int K, int gelu)
{
    __shared__ float As[8][128];
    __shared__ float Bs[8][128];
    const int bm = blockIdx.y * 128;
    const int bn = blockIdx.x * 128;
    const int t  = threadIdx.x;
    const int tx = t & 15, ty = t >> 4;

    float acc[8][8];
#pragma unroll
    for (int i = 0; i < 8; i++)
#pragma unroll
        for (int j = 0; j < 8; j++) acc[i][j] = 0.0f;

    const int arow = t >> 1, acol = (t & 1) * 4;
    const int brow = t >> 5, bcol = (t & 31) * 4;
    const float* Ap = A + (size_t)(bm + arow) * K + acol;
    const float* Bp = B + (size_t)brow * N + bn + bcol;

    for (int k0 = 0; k0 < K; k0 += 8) {
        float4 av = *(const float4*)(Ap + k0);
        float4 bv = *(const float4*)(Bp + (size_t)k0 * N);
        As[acol + 0][arow] = av.x; As[acol + 1][arow] = av.y;
        As[acol + 2][arow] = av.z; As[acol + 3][arow] = av.w;
        *(float4*)&Bs[brow][bcol] = bv;
        __syncthreads();
#pragma unroll
        for (int kk = 0; kk < 8; kk++) {
            float a[8], b[8];
            *(float4*)(a)     = *(float4*)&As[kk][ty * 8];
            *(float4*)(a + 4) = *(float4*)&As[kk][ty * 8 + 4];
            *(float4*)(b)     = *(float4*)&Bs[kk][tx * 8];
            *(float4*)(b + 4) = *(float4*)&Bs[kk][tx * 8 + 4];
#pragma unroll
            for (int i = 0; i < 8; i++)
#pragma unroll
                for (int j = 0; j < 8; j++) acc[i][j] += a[i] * b[j];
        }
        __syncthreads();
    }

#pragma unroll
    for (int i = 0; i < 8; i++) {
        const int row = bm + ty * 8 + i;
#pragma unroll
        for (int j = 0; j < 8; j++) {
            float v = acc[i][j] + bias[bn + tx * 8 + j];
            if (gelu) v = 0.5f * v * (1.0f + erff(v * 0.70710678118654752f));
            C[(size_t)row * N + bn + tx * 8 + j] = v;
        }
    }
}

// ---------------- per-(b,h) ksum / vmean ----------------
__global__ __launch_bounds__(256) void k_kstats()
{
    const int bh = blockIdx.x, b = bh >> 3, h = bh & 7;
    const int t = threadIdx.x;
    const int d = t & 63, c = t >> 6;
    float ks = 0.f, vs = 0.f;
    for (int n = c * 512; n < (c + 1) * 512; n++) {
        const float* p = g_qkv + (size_t)(b * SEQ + n) * QKVC + CMODEL + h * DK + d;
        ks += p[0];
        vs += p[CMODEL];
    }
    __shared__ float sk[256], sv[256];
    sk[t] = ks; sv[t] = vs;
    __syncthreads();
    if (t < 64) {
        float a = sk[t] + sk[t + 64] + sk[t + 128] + sk[t + 192];
        float v = sv[t] + sv[t + 64] + sv[t + 128] + sv[t + 192];
        g_ksum[bh * DK + t]  = a;
        g_vmean[bh * DK + t] = v * (1.0f / SEQ);
    }
}

// ---------------- streamed QK^T row-max + M (scalar fp32, selection-critical) ----------------
__global__ __launch_bounds__(256) void k_rowmax()
{
    const int bh = blockIdx.y, b = bh >> 3, h = bh & 7;
    const int bm = blockIdx.x * 128;
    const int t = threadIdx.x;
    const int tx = t & 15, ty = t >> 4;

    __shared__ float As[8][128];
    __shared__ float Bs[8][128];
    __shared__ float red[128][17];
    __shared__ float ks[64];
    if (t < 64) ks[t] = g_ksum[bh * DK + t];

    float lmax[8];
#pragma unroll
    for (int i = 0; i < 8; i++) lmax[i] = NEGINF;

    const int arow = t >> 1, acol = (t & 1) * 4;
    const float* qbase = g_qkv + (size_t)(b * SEQ) * QKVC + h * DK;
    const float* kbase = qbase + CMODEL;

    for (int m0 = 0; m0 < SEQ; m0 += 128) {
        float acc[8][8];
#pragma unroll
        for (int i = 0; i < 8; i++)
#pragma unroll
            for (int j = 0; j < 8; j++) acc[i][j] = 0.0f;

        for (int k0 = 0; k0 < DK; k0 += 8) {
            float4 av = *(const float4*)(qbase + (size_t)(bm + arow) * QKVC + k0 + acol);
            float4 bv = *(const float4*)(kbase + (size_t)(m0 + arow) * QKVC + k0 + acol);
            As[acol + 0][arow] = av.x; As[acol + 1][arow] = av.y;
            As[acol + 2][arow] = av.z; As[acol + 3][arow] = av.w;
            Bs[acol + 0][arow] = bv.x; Bs[acol + 1][arow] = bv.y;
            Bs[acol + 2][arow] = bv.z; Bs[acol + 3][arow] = bv.w;
            __syncthreads();
#pragma unroll
            for (int kk = 0; kk < 8; kk++) {
                float a[8], bb[8];
                *(float4*)(a)      = *(float4*)&As[kk][ty * 8];
                *(float4*)(a + 4)  = *(float4*)&As[kk][ty * 8 + 4];
                *(float4*)(bb)     = *(float4*)&Bs[kk][tx * 8];
                *(float4*)(bb + 4) = *(float4*)&Bs[kk][tx * 8 + 4];
#pragma unroll
                for (int i = 0; i < 8; i++)
#pragma unroll
                    for (int j = 0; j < 8; j++) acc[i][j] += a[i] * bb[j];
            }
            __syncthreads();
        }
#pragma unroll
        for (int i = 0; i < 8; i++) {
            float mx = acc[i][0];
#pragma unroll
            for (int j = 1; j < 8; j++) mx = fmaxf(mx, acc[i][j]);
            lmax[i] = fmaxf(lmax[i], mx);
        }
    }

#pragma unroll
    for (int i = 0; i < 8; i++) red[ty * 8 + i][tx] = lmax[i];
    __syncthreads();
    if (t < 128) {
        float mx = red[t][0];
#pragma unroll
        for (int j = 1; j < 16; j++) mx = fmaxf(mx, red[t][j]);
        float qd = 0.f;
        const float* qp = qbase + (size_t)(bm + t) * QKVC;
#pragma unroll 8
        for (int d = 0; d < 64; d++) qd += qp[d] * ks[d];
        g_rowmax[bh * SEQ + bm + t] = SCALE * mx;
        g_M[bh * SEQ + bm + t]      = SCALE * mx - SCALE * qd * (1.0f / SEQ);
    }
}

// ---------------- exact top-512 per (b,h): in-smem bitonic sort (jax tie-break) ----------------
__global__ __launch_bounds__(1024) void k_topk()
{
    const int bh = blockIdx.x;
    const int t = threadIdx.x;
    __shared__ float sv[2048];
    __shared__ int   si[2048];
    sv[t]        = g_M[bh * SEQ + t];        si[t]        = t;
    sv[t + 1024] = g_M[bh * SEQ + t + 1024]; si[t + 1024] = t + 1024;

    for (int k = 2; k <= 2048; k <<= 1) {
        for (int j = k >> 1; j > 0; j >>= 1) {
            __syncthreads();
#pragma unroll 1
            for (int e = t; e < 2048; e += 1024) {
                const int p = e ^ j;
                if (p > e) {
                    float va = sv[e], vb = sv[p];
                    int   ia = si[e], ib = si[p];
                    bool gtr = (va > vb) || (va == vb && ia < ib);
                    bool desc = ((e & k) == 0);
                    if (desc ? !gtr : gtr) {
                        sv[e] = vb; sv[p] = va;
                        si[e] = ib; si[p] = ia;
                    }
                }
            }
        }
    }
    __syncthreads();
    if (t < NTOP) g_topidx[bh * NTOP + t] = si[t];
}

// ---------------- fill all rows with vmean ----------------
__global__ __launch_bounds__(256) void k_fill()
{
    const int i = blockIdx.x * 256 + threadIdx.x;
    const int c = i & 511;
    const int tok = i >> 9;
    const int b = tok >> 11;
    g_attnO[i] = g_vmean[(b * NHEADS + (c >> 6)) * DK + (c & 63)];
}

// ---------------- softmax @ V for selected rows ----------------
__global__ __launch_bounds__(128) void k_attn_sel()
{
    const int bh = blockIdx.y, b = bh >> 3, h = bh & 7;
    const int t = threadIdx.x;

    __shared__ float Qs[16][65];
    __shared__ float Ks[64][65];
    __shared__ float Vs[64][65];
    __shared__ float Se[16][64];
    __shared__ float sume[16];
    __shared__ float rmax[16];
    __shared__ int   nidx[16];

    if (t < 16) {
        int n = g_topidx[bh * NTOP + blockIdx.x * 16 + t];
        nidx[t] = n;
        sume[t] = 0.f;
        rmax[t] = g_rowmax[bh * SEQ + n];
    }
    __syncthreads();

    const int r  = t >> 3;
    const int mg = (t & 7) * 8;
    const int dg = (t & 7) * 8;

    {
        const int qr = t >> 3, c0 = (t & 7) * 8;
        const float* qp = g_qkv + (size_t)(b * SEQ + nidx[qr]) * QKVC + h * DK + c0;
        float4 q0 = *(const float4*)qp, q1 = *(const float4*)(qp + 4);
        Qs[qr][c0 + 0] = q0.x; Qs[qr][c0 + 1] = q0.y; Qs[qr][c0 + 2] = q0.z; Qs[qr][c0 + 3] = q0.w;
        Qs[qr][c0 + 4] = q1.x; Qs[qr][c0 + 5] = q1.y; Qs[qr][c0 + 6] = q1.z; Qs[qr][c0 + 7] = q1.w;
    }
    const float rm = rmax[r];

    float o[8];
#pragma unroll
    for (int i = 0; i < 8; i++) o[i] = 0.f;

    for (int m0 = 0; m0 < SEQ; m0 += 64) {
        __syncthreads();
        for (int f = t; f < 1024; f += 128) {
            const int mr = f >> 4, c4 = (f & 15) * 4;
            const float* kp = g_qkv + (size_t)(b * SEQ + m0 + mr) * QKVC + CMODEL + h * DK + c4;
            float4 kv = *(const float4*)kp;
            float4 vv = *(const float4*)(kp + CMODEL);
            Ks[mr][c4 + 0] = kv.x; Ks[mr][c4 + 1] = kv.y; Ks[mr][c4 + 2] = kv.z; Ks[mr][c4 + 3] = kv.w;
            Vs[mr][c4 + 0] = vv.x; Vs[mr][c4 + 1] = vv.y; Vs[mr][c4 + 2] = vv.z; Vs[mr][c4 + 3] = vv.w;
        }
        __syncthreads();

        float s[8];
#pragma unroll
        for (int jj = 0; jj < 8; jj++) s[jj] = 0.f;
#pragma unroll 8
        for (int d = 0; d < 64; d++) {
            const float qv = Qs[r][d];
#pragma unroll
            for (int jj = 0; jj < 8; jj++) s[jj] += qv * Ks[mg + jj][d];
        }
        float lsum = 0.f;
#pragma unroll
        for (int jj = 0; jj < 8; jj++) {
            float ev = expf(s[jj] * SCALE - rm);
            Se[r][mg + jj] = ev;
            lsum += ev;
        }
        atomicAdd(&sume[r], lsum);
        __syncthreads();

#pragma unroll 8
        for (int m = 0; m < 64; m++) {
            const float ev = Se[r][m];
#pragma unroll
            for (int i = 0; i < 8; i++) o[i] += ev * Vs[m][dg + i];
        }
    }
    __syncthreads();
    const float inv = 1.0f / sume[r];
    float* op = g_attnO + (size_t)(b * SEQ + nidx[r]) * CMODEL + h * DK + dg;
#pragma unroll
    for (int i = 0; i < 8; i++) op[i] = o[i] * inv;
}

// ---------------- fused residual add + LayerNorm over C=512 ----------------
__global__ __launch_bounds__(128) void k_addln(
    const float* __restrict__ A, const float* __restrict__ Bv,
    const float* __restrict__ g, const float* __restrict__ be, float* __restrict__ O)
{
    const int row = blockIdx.x, t = threadIdx.x;
    float4 a = ((const float4*)(A  + (size_t)row * CMODEL))[t];
    float4 b = ((const float4*)(Bv + (size_t)row * CMODEL))[t];
    float v0 = a.x + b.x, v1 = a.y + b.y, v2 = a.z + b.z, v3 = a.w + b.w;

    __shared__ float ws[4];
    float s = v0 + v1 + v2 + v3;
#pragma unroll
    for (int o = 16; o > 0; o >>= 1) s += __shfl_xor_sync(0xffffffffu, s, o);
    if ((t & 31) == 0) ws[t >> 5] = s;
    __syncthreads();
    const float mean = (ws[0] + ws[1] + ws[2] + ws[3]) * (1.0f / CMODEL);
    v0 -= mean; v1 -= mean; v2 -= mean; v3 -= mean;
    float q = v0 * v0 + v1 * v1 + v2 * v2 + v3 * v3;
#pragma unroll
    for (int o = 16; o > 0; o >>= 1) q += __shfl_xor_sync(0xffffffffu, q, o);
    __syncthreads();
    if ((t & 31) == 0) ws[t >> 5] = q;
    __syncthreads();
    const float var = (ws[0] + ws[1] + ws[2] + ws[3]) * (1.0f / CMODEL);
    const float rs = rsqrtf(var + LNEPS);
    float4 gg = ((const float4*)g)[t], bb = ((const float4*)be)[t];
    float4 out;
    out.x = v0 * rs * gg.x + bb.x;
    out.y = v1 * rs * gg.y + bb.y;
    out.z = v2 * rs * gg.z + bb.z;
    out.w = v3 * rs * gg.w + bb.w;
    ((float4*)(O + (size_t)row * CMODEL))[t] = out;
}

// ---------------- conv weight repack ----------------
__global__ __launch_bounds__(256) void k_packW(const float* __restrict__ conv_w)
{
    const int i = blockIdx.x * 256 + threadIdx.x;
    const int co = i & 511;
    const int rr = i >> 9;
    const int ci = rr & 511;
    const int k  = rr >> 9;
    g_wr[i] = conv_w[(co * CMODEL + ci) * 3 + k];
}

// ---------------- circular-shift pack of x2 ----------------
__global__ __launch_bounds__(256) void k_packX()
{
    const int i = blockIdx.x * 256 + threadIdx.x;
    const int col = i % QKVC;
    const int tok = i / QKVC;
    const int b = tok >> 11, n = tok & 2047;
    const int k = col >> 9, ci = col & 511;
    const int ns = (n - 1 + k + SEQ) & (SEQ - 1);
    g_qkv[i] = g_x2[(size_t)(b * SEQ + ns) * CMODEL + ci];
}

// ---------------- maxpool + ELU + LayerNorm -> final output ----------------
__global__ __launch_bounds__(128) void k_poolln(
    const float* __restrict__ Y, const float* __restrict__ g,
    const float* __restrict__ be, float* __restrict__ O)
{
    const int row = blockIdx.x;
    const int b = row >> 10, j = row & 1023;
    const int t = threadIdx.x;
    const int c = t * 4;

    float m0 = NEGINF, m1 = NEGINF, m2 = NEGINF, m3 = NEGINF;
#pragma unroll
    for (int dn = 0; dn < 3; dn++) {
        const int n = 2 * j - 1 + dn;
        if (n >= 0 && n < SEQ) {
            float4 w = *(const float4*)(Y + (size_t)(b * SEQ + n) * CMODEL + c);
            m0 = fmaxf(m0, w.x); m1 = fmaxf(m1, w.y);
            m2 = fmaxf(m2, w.z); m3 = fmaxf(m3, w.w);
        }
    }
    float v0 = m0 > 0.f ? m0 : expm1f(m0);
    float v1 = m1 > 0.f ? m1 : expm1f(m1);
    float v2 = m2 > 0.f ? m2 : expm1f(m2);
    float v3 = m3 > 0.f ? m3 : expm1f(m3);

    __shared__ float ws[4];
    float s = v0 + v1 + v2 + v3;
#pragma unroll
    for (int o = 16; o > 0; o >>= 1) s += __shfl_xor_sync(0xffffffffu, s, o);
    if ((t & 31) == 0) ws[t >> 5] = s;
    __syncthreads();
    const float mean = (ws[0] + ws[1] + ws[2] + ws[3]) * (1.0f / CMODEL);
    v0 -= mean; v1 -= mean; v2 -= mean; v3 -= mean;
    float q = v0 * v0 + v1 * v1 + v2 * v2 + v3 * v3;
#pragma unroll
    for (int o = 16; o > 0; o >>= 1) q += __shfl_xor_sync(0xffffffffu, q, o);
    __syncthreads();
    if ((t & 31) == 0) ws[t >> 5] = q;
    __syncthreads();
    const float var = (ws[0] + ws[1] + ws[2] + ws[3]) * (1.0f / CMODEL);
    const float rs = rsqrtf(var + LNEPS);
    float4 gg = ((const float4*)g)[t], bb = ((const float4*)be)[t];
    float4 out;
    out.x = v0 * rs * gg.x + bb.x;
    out.y = v1 * rs * gg.y + bb.y;
    out.z = v2 * rs * gg.z + bb.z;
    out.w = v3 * rs * gg.w + bb.w;
    ((float4*)(O + (size_t)row * CMODEL))[t] = out;
}

// ---------------- host orchestration ----------------
extern "C" void kernel_launch(void* const* d_in, const int* in_sizes, int n_in,
                              void* d_out, int out_size)
{
    (void)in_sizes; (void)n_in; (void)out_size;
    const float* x      = (const float*)d_in[0];
    const float* qkv_w  = (const float*)d_in[1];
    const float* qkv_b  = (const float*)d_in[2];
    const float* out_w  = (const float*)d_in[3];
    const float* out_b  = (const float*)d_in[4];
    const float* ffn_w1 = (const float*)d_in[5];
    const float* ffn_b1 = (const float*)d_in[6];
    const float* ffn_w2 = (const float*)d_in[7];
    const float* ffn_b2 = (const float*)d_in[8];
    const float* n1_g   = (const float*)d_in[9];
    const float* n1_b   = (const float*)d_in[10];
    const float* n2_g   = (const float*)d_in[11];
    const float* n2_b   = (const float*)d_in[12];
    const float* conv_w = (const float*)d_in[13];
    const float* conv_b = (const float*)d_in[14];
    const float* cn_g   = (const float*)d_in[15];
    const float* cn_b   = (const float*)d_in[16];
    float* out = (float*)d_out;

    float *p_qkv, *p_hff, *p_attnO, *p_t1, *p_x1, *p_x2, *p_cy, *p_wr;
    __nv_bfloat16 *p_ah, *p_al, *p_bh, *p_bl;
    cudaGetSymbolAddress((void**)&p_qkv,   g_qkv);
    cudaGetSymbolAddress((void**)&p_hff,   g_hff);
    cudaGetSymbolAddress((void**)&p_attnO, g_attnO);
    cudaGetSymbolAddress((void**)&p_t1,    g_t1);
    cudaGetSymbolAddress((void**)&p_x1,    g_x1);
    cudaGetSymbolAddress((void**)&p_x2,    g_x2);
    cudaGetSymbolAddress((void**)&p_cy,    g_cy);
    cudaGetSymbolAddress((void**)&p_wr,    g_wr);
    cudaGetSymbolAddress((void**)&p_ah,    g_ah);
    cudaGetSymbolAddress((void**)&p_al,    g_al);
    cudaGetSymbolAddress((void**)&p_bh,    g_bh);
    cudaGetSymbolAddress((void**)&p_bl,    g_bl);

    // 1) QKV projection (scalar fp32 — q/k accuracy is selection-critical)
    k_sgemm<<<dim3(QKVC / 128, NTOK / 128), 256>>>(x, qkv_w, qkv_b, p_qkv, NTOK, QKVC, CMODEL, 0);
    // 2) per-head key-sum / value-mean
    k_kstats<<<BATCH * NHEADS, 256>>>();
    // 3) streamed row-max of QK^T and sparsity measure M (scalar fp32)
    k_rowmax<<<dim3(SEQ / 128, BATCH * NHEADS), 256>>>();
    // 4) exact top-512 per head
    k_topk<<<BATCH * NHEADS, 1024>>>();
    // 5) uniform rows = vmean, then real softmax for selected rows
    k_fill<<<(NTOK * CMODEL) / 256, 256>>>();
    k_attn_sel<<<dim3(NTOP / 16, BATCH * NHEADS), 128>>>();
    // 6) output projection (tensor, split-bf16) + LN1
    k_cvt<<<(NTOK * CMODEL) / 256, 256>>>(p_attnO, p_ah, p_al, NTOK * CMODEL);
    k_cvt<<<(CMODEL * CMODEL) / 256, 256>>>(out_w, p_bh, p_bl, CMODEL * CMODEL);
    k_hgemm<<<dim3(CMODEL / 128, NTOK / 128), 256>>>(p_ah, p_al, p_bh, p_bl, out_b, p_t1, NTOK, CMODEL, CMODEL, 0);
    k_addln<<<NTOK, 128>>>(x, p_t1, n1_g, n1_b, p_x1);
    // 7) FFN (tensor) + LN2
    k_cvt<<<(NTOK * CMODEL) / 256, 256>>>(p_x1, p_ah, p_al, NTOK * CMODEL);
    k_cvt<<<(CMODEL * DFF) / 256, 256>>>(ffn_w1, p_bh, p_bl, CMODEL * DFF);
    k_hgemm<<<dim3(DFF / 128, NTOK / 128), 256>>>(p_ah, p_al, p_bh, p_bl, ffn_b1, p_hff, NTOK, DFF, CMODEL, 1);
    k_cvt<<<(NTOK * DFF) / 256, 256>>>(p_hff, p_ah, p_al, NTOK * DFF);
    k_cvt<<<(DFF * CMODEL) / 256, 256>>>(ffn_w2, p_bh, p_bl, DFF * CMODEL);
    k_hgemm<<<dim3(CMODEL / 128, NTOK / 128), 256>>>(p_ah, p_al, p_bh, p_bl, ffn_b2, p_t1, NTOK, CMODEL, DFF, 0);
    k_addln<<<NTOK, 128>>>(p_x1, p_t1, n2_g, n2_b, p_x2);
    // 8) circular conv1d(k=3) as tensor GEMM over packed input
    k_packW<<<(3 * CMODEL * CMODEL) / 256, 256>>>(conv_w);
    k_packX<<<(NTOK * QKVC) / 256, 256>>>();
    k_cvt<<<(NTOK * QKVC) / 256, 256>>>(p_qkv, p_ah, p_al, NTOK * QKVC);
    k_cvt<<<(3 * CMODEL * CMODEL) / 256, 256>>>(p_wr, p_bh, p_bl, 3 * CMODEL * CMODEL);
    k_hgemm<<<dim3(CMODEL / 128, NTOK / 128), 256>>>(p_ah, p_al, p_bh, p_bl, conv_b, p_cy, NTOK, CMODEL, 3 * CMODEL, 0);
    // 9) maxpool + ELU + LN -> d_out
    k_poolln<<<BATCH * (SEQ / 2), 128>>>(p_cy, cn_g, cn_b, out);
}

// round 8
// speedup vs baseline: 2.4233x; 1.7394x over previous
#include <cuda_runtime.h>
#include <cuda_bf16.h>
#include <math.h>
#include <stdint.h>

#define BATCH   2
#define SEQ     2048
#define CMODEL  512
#define NHEADS  8
#define DK      64
#define DFF     2048
#define QKVC    1536
#define NTOK    (BATCH*SEQ)     /* 4096 */
#define NTOP    512
#define SCALE   0.125f
#define LNEPS   1e-5f
#define NEGINF  -3.402823466e38f

// ---------------- scratch (static device globals; no allocation) ----------------
__device__ float g_qkv[NTOK*QKVC];
__device__ float g_hff[NTOK*DFF];
__device__ float g_attnO[NTOK*CMODEL];
__device__ float g_t1[NTOK*CMODEL];
__device__ float g_x1[NTOK*CMODEL];
__device__ float g_x2[NTOK*CMODEL];
__device__ float g_cy[NTOK*CMODEL];
__device__ float g_wr[3*CMODEL*CMODEL];
__device__ float g_rowmax[BATCH*NHEADS*SEQ];
__device__ float g_M[BATCH*NHEADS*SEQ];
__device__ float g_ksum[BATCH*NHEADS*DK];
__device__ float g_vmean[BATCH*NHEADS*DK];
__device__ int   g_topidx[BATCH*NHEADS*NTOP];
// split-bf16 operand buffers (row-major, same layouts as R4)
__device__ __nv_bfloat16 g_ah[NTOK*DFF];
__device__ __nv_bfloat16 g_al[NTOK*DFF];
__device__ __nv_bfloat16 g_bh[DFF*CMODEL];
__device__ __nv_bfloat16 g_bl[DFF*CMODEL];

// ---------------- small PTX helpers ----------------
__device__ __forceinline__ uint32_t smem_u32(const void* p) {
    return (uint32_t)__cvta_generic_to_shared(p);
}
__device__ __forceinline__ void cpa16(void* dst, const void* src) {
    asm volatile("cp.async.cg.shared.global [%0], [%1], 16;"
                 :: "r"(smem_u32(dst)), "l"(src));
}
__device__ __forceinline__ void mma16816(float* c, const unsigned* a, const unsigned* b) {
    asm volatile(
        "mma.sync.aligned.m16n8k16.row.col.f32.bf16.bf16.f32 "
        "{%0,%1,%2,%3}, {%4,%5,%6,%7}, {%8,%9}, {%0,%1,%2,%3};"
        : "+f"(c[0]), "+f"(c[1]), "+f"(c[2]), "+f"(c[3])
        : "r"(a[0]), "r"(a[1]), "r"(a[2]), "r"(a[3]), "r"(b[0]), "r"(b[1]));
}
__device__ __forceinline__ void ldsm4(unsigned* r, const void* p) {
    asm volatile("ldmatrix.sync.aligned.m8n8.x4.shared.b16 {%0,%1,%2,%3}, [%4];"
                 : "=r"(r[0]), "=r"(r[1]), "=r"(r[2]), "=r"(r[3]) : "r"(smem_u32(p)));
}
__device__ __forceinline__ void ldsm4t(unsigned* r, const void* p) {
    asm volatile("ldmatrix.sync.aligned.m8n8.x4.trans.shared.b16 {%0,%1,%2,%3}, [%4];"
                 : "=r"(r[0]), "=r"(r[1]), "=r"(r[2]), "=r"(r[3]) : "r"(smem_u32(p)));
}

// ---------------- pipelined split-bf16 tensor GEMM ----------------
// C[M,N] = Ah@Bh + Ah@Bl + Al@Bh + bias (opt exact GELU)
// A row-major [M,K] hi/lo; B row-major [K,N] hi/lo. BM=BN=128, BK=32, 2-stage cp.async.
#define AP 40
#define BP 136
#define ST_BYTES 37888          /* per-stage: A 2*10240 + B 2*8704 */
#define SO_AH 0
#define SO_AL 10240
#define SO_BH 20480
#define SO_BL 29184
#define HG_SMEM (2*ST_BYTES)

__global__ __launch_bounds__(256) void k_hgemm(
    const __nv_bfloat16* __restrict__ Agh, const __nv_bfloat16* __restrict__ Agl,
    const __nv_bfloat16* __restrict__ Bgh, const __nv_bfloat16* __restrict__ Bgl,
    const float* __restrict__ bias, float* __restrict__ C,
    int M, int N, int K, int gelu)
{
    extern __shared__ __align__(16) char sm_[];
    const int t = threadIdx.x;
    const int warp = t >> 5, lane = t & 31;
    const int wm = warp >> 1, wn = warp & 1;
    const int bm = blockIdx.y * 128, bn = blockIdx.x * 128;

    float acc[2][8][4];
#pragma unroll
    for (int i = 0; i < 2; i++)
#pragma unroll
        for (int j = 0; j < 8; j++)
#pragma unroll
            for (int q = 0; q < 4; q++) acc[i][j][q] = 0.f;

    const int ar0 = t >> 2, ac0 = (t & 3) * 8;
    const int br0 = t >> 4, bc0 = (t & 15) * 8;
    const int nch = K >> 5;

    // stage loader: 8 cp.async (128B) per thread
    auto load = [&](int s, int c) {
        char* sp = sm_ + s * ST_BYTES;
        const int k0 = c << 5;
#pragma unroll
        for (int i = 0; i < 2; i++) {
            const int r = ar0 + i * 64;
            cpa16(sp + SO_AH + (r * AP + ac0) * 2, Agh + (size_t)(bm + r) * K + k0 + ac0);
            cpa16(sp + SO_AL + (r * AP + ac0) * 2, Agl + (size_t)(bm + r) * K + k0 + ac0);
        }
#pragma unroll
        for (int i = 0; i < 2; i++) {
            const int r = br0 + i * 16;
            cpa16(sp + SO_BH + (r * BP + bc0) * 2, Bgh + (size_t)(k0 + r) * N + bn + bc0);
            cpa16(sp + SO_BL + (r * BP + bc0) * 2, Bgl + (size_t)(k0 + r) * N + bn + bc0);
        }
        asm volatile("cp.async.commit_group;" ::: "memory");
    };

    load(0, 0);
    for (int c = 0; c < nch; c++) {
        if (c + 1 < nch) {
            load((c + 1) & 1, c + 1);
            asm volatile("cp.async.wait_group 1;" ::: "memory");
        } else {
            asm volatile("cp.async.wait_group 0;" ::: "memory");
        }
        __syncthreads();

        char* sp = sm_ + (c & 1) * ST_BYTES;
        const __nv_bfloat16 (*Ah)[AP] = (const __nv_bfloat16 (*)[AP])(sp + SO_AH);
        const __nv_bfloat16 (*Al)[AP] = (const __nv_bfloat16 (*)[AP])(sp + SO_AL);
        const __nv_bfloat16 (*Bh)[BP] = (const __nv_bfloat16 (*)[BP])(sp + SO_BH);
        const __nv_bfloat16 (*Bl)[BP] = (const __nv_bfloat16 (*)[BP])(sp + SO_BL);

#pragma unroll
        for (int ks = 0; ks < 32; ks += 16) {
            unsigned ah[2][4], al[2][4];
#pragma unroll
            for (int mt = 0; mt < 2; mt++) {
                const int r = wm * 32 + mt * 16 + (lane & 15);
                const int cc = ks + (lane >> 4) * 8;
                ldsm4(ah[mt], &Ah[r][cc]);
                ldsm4(al[mt], &Al[r][cc]);
            }
#pragma unroll
            for (int np = 0; np < 4; np++) {
                unsigned bh[4], bl[4];
                const int r = ks + (lane & 15);
                const int cc = wn * 64 + np * 16 + (lane >> 4) * 8;
                ldsm4t(bh, &Bh[r][cc]);
                ldsm4t(bl, &Bl[r][cc]);
#pragma unroll
                for (int mt = 0; mt < 2; mt++) {
                    mma16816(acc[mt][2 * np],     ah[mt], bh);
                    mma16816(acc[mt][2 * np],     ah[mt], bl);
                    mma16816(acc[mt][2 * np],     al[mt], bh);
                    mma16816(acc[mt][2 * np + 1], ah[mt], bh + 2);
                    mma16816(acc[mt][2 * np + 1], ah[mt], bl + 2);
                    mma16816(acc[mt][2 * np + 1], al[mt], bh + 2);
                }
            }
        }
        __syncthreads();
    }

    // epilogue (same mapping as R4)
    const int g = lane >> 2, tg = lane & 3;
#pragma unroll
    for (int mt = 0; mt < 2; mt++) {
#pragma unroll
        for (int nt = 0; nt < 8; nt++) {
            const int col = bn + wn * 64 + nt * 8 + 2 * tg;
            const float b0 = bias[col], b1 = bias[col + 1];
#pragma unroll
            for (int hrow = 0; hrow < 2; hrow++) {
                const int row = bm + wm * 32 + mt * 16 + g + hrow * 8;
                float v0 = acc[mt][nt][2 * hrow]     + b0;
                float v1 = acc[mt][nt][2 * hrow + 1] + b1;
                if (gelu) {
                    v0 = 0.5f * v0 * (1.0f + erff(v0 * 0.70710678118654752f));
                    v1 = 0.5f * v1 * (1.0f + erff(v1 * 0.70710678118654752f));
                }
                *(float2*)(C + (size_t)row * N + col) = make_float2(v0, v1);
            }
        }
    }
}

// ---------------- fp32 -> (hi,lo) bf16 split ----------------
__global__ __launch_bounds__(256) void k_cvt(
    const float* __restrict__ s, __nv_bfloat16* __restrict__ hi,
    __nv_bfloat16* __restrict__ lo, int n)
{
    const int i = blockIdx.x * 256 + threadIdx.x;
    if (i < n) {
        float x = s[i];
        __nv_bfloat16 h = __float2bfloat16_rn(x);
        hi[i] = h;
        lo[i] = __float2bfloat16_rn(x - __bfloat162float(h));
    }
}

// ---------------- scalar fp32 SGEMM (selection-critical QKV) ----------------
__global__ __launch_bounds__(256) void k_sgemm(
    const float* __restrict__ A, const float* __restrict__ B,
    const float* __restrict__ bias, float* __restrict__ C,
    int M, int N, int K, int gelu)
{
    __shared__ float As[8][128];
    __shared__ float Bs[8][128];
    const int bm = blockIdx.y * 128;
    const int bn = blockIdx.x * 128;
    const int t  = threadIdx.x;
    const int tx = t & 15, ty = t >> 4;

    float acc[8][8];
#pragma unroll
    for (int i = 0; i < 8; i++)
#pragma unroll
        for (int j = 0; j < 8; j++) acc[i][j] = 0.0f;

    const int arow = t >> 1, acol = (t & 1) * 4;
    const int brow = t >> 5, bcol = (t & 31) * 4;
    const float* Ap = A + (size_t)(bm + arow) * K + acol;
    const float* Bp = B + (size_t)brow * N + bn + bcol;

    for (int k0 = 0; k0 < K; k0 += 8) {
        float4 av = *(const float4*)(Ap + k0);
        float4 bv = *(const float4*)(Bp + (size_t)k0 * N);
        As[acol + 0][arow] = av.x; As[acol + 1][arow] = av.y;
        As[acol + 2][arow] = av.z; As[acol + 3][arow] = av.w;
        *(float4*)&Bs[brow][bcol] = bv;
        __syncthreads();
#pragma unroll
        for (int kk = 0; kk < 8; kk++) {
            float a[8], b[8];
            *(float4*)(a)     = *(float4*)&As[kk][ty * 8];
            *(float4*)(a + 4) = *(float4*)&As[kk][ty * 8 + 4];
            *(float4*)(b)     = *(float4*)&Bs[kk][tx * 8];
            *(float4*)(b + 4) = *(float4*)&Bs[kk][tx * 8 + 4];
#pragma unroll
            for (int i = 0; i < 8; i++)
#pragma unroll
                for (int j = 0; j < 8; j++) acc[i][j] += a[i] * b[j];
        }
        __syncthreads();
    }

#pragma unroll
    for (int i = 0; i < 8; i++) {
        const int row = bm + ty * 8 + i;
#pragma unroll
        for (int j = 0; j < 8; j++) {
            float v = acc[i][j] + bias[bn + tx * 8 + j];
            if (gelu) v = 0.5f * v * (1.0f + erff(v * 0.70710678118654752f));
            C[(size_t)row * N + bn + tx * 8 + j] = v;
        }
    }
}

// ---------------- per-(b,h) ksum / vmean ----------------
__global__ __launch_bounds__(256) void k_kstats()
{
    const int bh = blockIdx.x, b = bh >> 3, h = bh & 7;
    const int t = threadIdx.x;
    const int d = t & 63, c = t >> 6;
    float ks = 0.f, vs = 0.f;
    for (int n = c * 512; n < (c + 1) * 512; n++) {
        const float* p = g_qkv + (size_t)(b * SEQ + n) * QKVC + CMODEL + h * DK + d;
        ks += p[0];
        vs += p[CMODEL];
    }
    __shared__ float sk[256], sv[256];
    sk[t] = ks; sv[t] = vs;
    __syncthreads();
    if (t < 64) {
        float a = sk[t] + sk[t + 64] + sk[t + 128] + sk[t + 192];
        float v = sv[t] + sv[t + 64] + sv[t + 128] + sv[t + 192];
        g_ksum[bh * DK + t]  = a;
        g_vmean[bh * DK + t] = v * (1.0f / SEQ);
    }
}

// ---------------- streamed QK^T row-max + M: Q preloaded, 64-deep K tiles ----------------
// smem floats: Qs[64][128] | Ks[64][128] | red[128][17] | ks[64]
#define RM_SMEM ((2*64*128 + 128*17 + 64) * 4)
__global__ __launch_bounds__(256) void k_rowmax()
{
    extern __shared__ float rs_[];
    float (*Qs)[128] = (float (*)[128])rs_;
    float (*Ks)[128] = (float (*)[128])(rs_ + 64 * 128);
    float (*red)[17] = (float (*)[17])(rs_ + 2 * 64 * 128);
    float* ks = rs_ + 2 * 64 * 128 + 128 * 17;

    const int bh = blockIdx.y, b = bh >> 3, h = bh & 7;
    const int bm = blockIdx.x * 128;
    const int t = threadIdx.x;
    const int tx = t & 15, ty = t >> 4;
    const int arow = t >> 1, acol = (t & 1) * 4;

    const float* qbase = g_qkv + (size_t)(b * SEQ) * QKVC + h * DK;
    const float* kbase = qbase + CMODEL;

    if (t < 64) ks[t] = g_ksum[bh * DK + t];
    // Q tile once: rows bm..bm+127, all 64 dk
#pragma unroll
    for (int k0 = 0; k0 < DK; k0 += 8) {
        float4 av = *(const float4*)(qbase + (size_t)(bm + arow) * QKVC + k0 + acol);
        Qs[k0 + acol + 0][arow] = av.x; Qs[k0 + acol + 1][arow] = av.y;
        Qs[k0 + acol + 2][arow] = av.z; Qs[k0 + acol + 3][arow] = av.w;
    }

    float lmax[8];
#pragma unroll
    for (int i = 0; i < 8; i++) lmax[i] = NEGINF;

    for (int m0 = 0; m0 < SEQ; m0 += 128) {
        __syncthreads();   // Ks consumers of previous tile done (also covers Qs ready 1st iter)
#pragma unroll
        for (int k0 = 0; k0 < DK; k0 += 8) {
            float4 bv = *(const float4*)(kbase + (size_t)(m0 + arow) * QKVC + k0 + acol);
            Ks[k0 + acol + 0][arow] = bv.x; Ks[k0 + acol + 1][arow] = bv.y;
            Ks[k0 + acol + 2][arow] = bv.z; Ks[k0 + acol + 3][arow] = bv.w;
        }
        __syncthreads();

        float acc[8][8];
#pragma unroll
        for (int i = 0; i < 8; i++)
#pragma unroll
            for (int j = 0; j < 8; j++) acc[i][j] = 0.0f;

#pragma unroll 8
        for (int kk = 0; kk < DK; kk++) {
            float a[8], bb[8];
            *(float4*)(a)      = *(float4*)&Qs[kk][ty * 8];
            *(float4*)(a + 4)  = *(float4*)&Qs[kk][ty * 8 + 4];
            *(float4*)(bb)     = *(float4*)&Ks[kk][tx * 8];
            *(float4*)(bb + 4) = *(float4*)&Ks[kk][tx * 8 + 4];
#pragma unroll
            for (int i = 0; i < 8; i++)
#pragma unroll
                for (int j = 0; j < 8; j++) acc[i][j] += a[i] * bb[j];
        }
#pragma unroll
        for (int i = 0; i < 8; i++) {
            float mx = acc[i][0];
#pragma unroll
            for (int j = 1; j < 8; j++) mx = fmaxf(mx, acc[i][j]);
            lmax[i] = fmaxf(lmax[i], mx);
        }
    }

    __syncthreads();
#pragma unroll
    for (int i = 0; i < 8; i++) red[ty * 8 + i][tx] = lmax[i];
    __syncthreads();
    if (t < 128) {
        float mx = red[t][0];
#pragma unroll
        for (int j = 1; j < 16; j++) mx = fmaxf(mx, red[t][j]);
        float qd = 0.f;
        const float* qp = qbase + (size_t)(bm + t) * QKVC;
#pragma unroll 8
        for (int d = 0; d < 64; d++) qd += qp[d] * ks[d];
        g_rowmax[bh * SEQ + bm + t] = SCALE * mx;
        g_M[bh * SEQ + bm + t]      = SCALE * mx - SCALE * qd * (1.0f / SEQ);
    }
}

// ---------------- exact top-512 per (b,h): in-smem bitonic sort ----------------
__global__ __launch_bounds__(1024) void k_topk()
{
    const int bh = blockIdx.x;
    const int t = threadIdx.x;
    __shared__ float sv[2048];
    __shared__ int   si[2048];
    sv[t]        = g_M[bh * SEQ + t];        si[t]        = t;
    sv[t + 1024] = g_M[bh * SEQ + t + 1024]; si[t + 1024] = t + 1024;

    for (int k = 2; k <= 2048; k <<= 1) {
        for (int j = k >> 1; j > 0; j >>= 1) {
            __syncthreads();
#pragma unroll 1
            for (int e = t; e < 2048; e += 1024) {
                const int p = e ^ j;
                if (p > e) {
                    float va = sv[e], vb = sv[p];
                    int   ia = si[e], ib = si[p];
                    bool gtr = (va > vb) || (va == vb && ia < ib);
                    bool desc = ((e & k) == 0);
                    if (desc ? !gtr : gtr) {
                        sv[e] = vb; sv[p] = va;
                        si[e] = ib; si[p] = ia;
                    }
                }
            }
        }
    }
    __syncthreads();
    if (t < NTOP) g_topidx[bh * NTOP + t] = si[t];
}

// ---------------- fill all rows with vmean ----------------
__global__ __launch_bounds__(256) void k_fill()
{
    const int i = blockIdx.x * 256 + threadIdx.x;
    const int c = i & 511;
    const int tok = i >> 9;
    const int b = tok >> 11;
    g_attnO[i] = g_vmean[(b * NHEADS + (c >> 6)) * DK + (c & 63)];
}

// ---------------- softmax @ V for selected rows ----------------
__global__ __launch_bounds__(128) void k_attn_sel()
{
    const int bh = blockIdx.y, b = bh >> 3, h = bh & 7;
    const int t = threadIdx.x;

    __shared__ float Qs[16][65];
    __shared__ float Ks[64][65];
    __shared__ float Vs[64][65];
    __shared__ float Se[16][64];
    __shared__ float sume[16];
    __shared__ float rmax[16];
    __shared__ int   nidx[16];

    if (t < 16) {
        int n = g_topidx[bh * NTOP + blockIdx.x * 16 + t];
        nidx[t] = n;
        sume[t] = 0.f;
        rmax[t] = g_rowmax[bh * SEQ + n];
    }
    __syncthreads();

    const int r  = t >> 3;
    const int mg = (t & 7) * 8;
    const int dg = (t & 7) * 8;

    {
        const int qr = t >> 3, c0 = (t & 7) * 8;
        const float* qp = g_qkv + (size_t)(b * SEQ + nidx[qr]) * QKVC + h * DK + c0;
        float4 q0 = *(const float4*)qp, q1 = *(const float4*)(qp + 4);
        Qs[qr][c0 + 0] = q0.x; Qs[qr][c0 + 1] = q0.y; Qs[qr][c0 + 2] = q0.z; Qs[qr][c0 + 3] = q0.w;
        Qs[qr][c0 + 4] = q1.x; Qs[qr][c0 + 5] = q1.y; Qs[qr][c0 + 6] = q1.z; Qs[qr][c0 + 7] = q1.w;
    }
    const float rm = rmax[r];

    float o[8];
#pragma unroll
    for (int i = 0; i < 8; i++) o[i] = 0.f;

    for (int m0 = 0; m0 < SEQ; m0 += 64) {
        __syncthreads();
        for (int f = t; f < 1024; f += 128) {
            const int mr = f >> 4, c4 = (f & 15) * 4;
            const float* kp = g_qkv + (size_t)(b * SEQ + m0 + mr) * QKVC + CMODEL + h * DK + c4;
            float4 kv = *(const float4*)kp;
            float4 vv = *(const float4*)(kp + CMODEL);
            Ks[mr][c4 + 0] = kv.x; Ks[mr][c4 + 1] = kv.y; Ks[mr][c4 + 2] = kv.z; Ks[mr][c4 + 3] = kv.w;
            Vs[mr][c4 + 0] = vv.x; Vs[mr][c4 + 1] = vv.y; Vs[mr][c4 + 2] = vv.z; Vs[mr][c4 + 3] = vv.w;
        }
        __syncthreads();

        float s[8];
#pragma unroll
        for (int jj = 0; jj < 8; jj++) s[jj] = 0.f;
#pragma unroll 8
        for (int d = 0; d < 64; d++) {
            const float qv = Qs[r][d];
#pragma unroll
            for (int jj = 0; jj < 8; jj++) s[jj] += qv * Ks[mg + jj][d];
        }
        float lsum = 0.f;
#pragma unroll
        for (int jj = 0; jj < 8; jj++) {
            float ev = expf(s[jj] * SCALE - rm);
            Se[r][mg + jj] = ev;
            lsum += ev;
        }
        atomicAdd(&sume[r], lsum);
        __syncthreads();

#pragma unroll 8
        for (int m = 0; m < 64; m++) {
            const float ev = Se[r][m];
#pragma unroll
            for (int i = 0; i < 8; i++) o[i] += ev * Vs[m][dg + i];
        }
    }
    __syncthreads();
    const float inv = 1.0f / sume[r];
    float* op = g_attnO + (size_t)(b * SEQ + nidx[r]) * CMODEL + h * DK + dg;
#pragma unroll
    for (int i = 0; i < 8; i++) op[i] = o[i] * inv;
}

// ---------------- fused residual add + LayerNorm over C=512 ----------------
__global__ __launch_bounds__(128) void k_addln(
    const float* __restrict__ A, const float* __restrict__ Bv,
    const float* __restrict__ g, const float* __restrict__ be, float* __restrict__ O)
{
    const int row = blockIdx.x, t = threadIdx.x;
    float4 a = ((const float4*)(A  + (size_t)row * CMODEL))[t];
    float4 b = ((const float4*)(Bv + (size_t)row * CMODEL))[t];
    float v0 = a.x + b.x, v1 = a.y + b.y, v2 = a.z + b.z, v3 = a.w + b.w;

    __shared__ float ws[4];
    float s = v0 + v1 + v2 + v3;
#pragma unroll
    for (int o = 16; o > 0; o >>= 1) s += __shfl_xor_sync(0xffffffffu, s, o);
    if ((t & 31) == 0) ws[t >> 5] = s;
    __syncthreads();
    const float mean = (ws[0] + ws[1] + ws[2] + ws[3]) * (1.0f / CMODEL);
    v0 -= mean; v1 -= mean; v2 -= mean; v3 -= mean;
    float q = v0 * v0 + v1 * v1 + v2 * v2 + v3 * v3;
#pragma unroll
    for (int o = 16; o > 0; o >>= 1) q += __shfl_xor_sync(0xffffffffu, q, o);
    __syncthreads();
    if ((t & 31) == 0) ws[t >> 5] = q;
    __syncthreads();
    const float var = (ws[0] + ws[1] + ws[2] + ws[3]) * (1.0f / CMODEL);
    const float rs = rsqrtf(var + LNEPS);
    float4 gg = ((const float4*)g)[t], bb = ((const float4*)be)[t];
    float4 out;
    out.x = v0 * rs * gg.x + bb.x;
    out.y = v1 * rs * gg.y + bb.y;
    out.z = v2 * rs * gg.z + bb.z;
    out.w = v3 * rs * gg.w + bb.w;
    ((float4*)(O + (size_t)row * CMODEL))[t] = out;
}

// ---------------- conv weight repack: wr[k*C+ci, co] = conv_w[co, ci, k] ----------------
__global__ __launch_bounds__(256) void k_packW(const float* __restrict__ conv_w)
{
    const int i = blockIdx.x * 256 + threadIdx.x;
    const int co = i & 511;
    const int rr = i >> 9;
    const int ci = rr & 511;
    const int k  = rr >> 9;
    g_wr[i] = conv_w[(co * CMODEL + ci) * 3 + k];
}

// ---------------- circular-shift pack of x2 -> split bf16 A [4096,1536] ----------------
__global__ __launch_bounds__(256) void k_packXcvt()
{
    const int i = blockIdx.x * 256 + threadIdx.x;
    const int col = i % QKVC, tok = i / QKVC;
    const int b = tok >> 11, n = tok & 2047;
    const int k = col >> 9, ci = col & 511;
    const int ns = (n - 1 + k + SEQ) & (SEQ - 1);
    float x = g_x2[(size_t)(b * SEQ + ns) * CMODEL + ci];
    __nv_bfloat16 h = __float2bfloat16_rn(x);
    g_ah[i] = h;
    g_al[i] = __float2bfloat16_rn(x - __bfloat162float(h));
}

// ---------------- maxpool + ELU + LayerNorm -> final output ----------------
__global__ __launch_bounds__(128) void k_poolln(
    const float* __restrict__ Y, const float* __restrict__ g,
    const float* __restrict__ be, float* __restrict__ O)
{
    const int row = blockIdx.x;
    const int b = row >> 10, j = row & 1023;
    const int t = threadIdx.x;
    const int c = t * 4;

    float m0 = NEGINF, m1 = NEGINF, m2 = NEGINF, m3 = NEGINF;
#pragma unroll
    for (int dn = 0; dn < 3; dn++) {
        const int n = 2 * j - 1 + dn;
        if (n >= 0 && n < SEQ) {
            float4 w = *(const float4*)(Y + (size_t)(b * SEQ + n) * CMODEL + c);
            m0 = fmaxf(m0, w.x); m1 = fmaxf(m1, w.y);
            m2 = fmaxf(m2, w.z); m3 = fmaxf(m3, w.w);
        }
    }
    float v0 = m0 > 0.f ? m0 : expm1f(m0);
    float v1 = m1 > 0.f ? m1 : expm1f(m1);
    float v2 = m2 > 0.f ? m2 : expm1f(m2);
    float v3 = m3 > 0.f ? m3 : expm1f(m3);

    __shared__ float ws[4];
    float s = v0 + v1 + v2 + v3;
#pragma unroll
    for (int o = 16; o > 0; o >>= 1) s += __shfl_xor_sync(0xffffffffu, s, o);
    if ((t & 31) == 0) ws[t >> 5] = s;
    __syncthreads();
    const float mean = (ws[0] + ws[1] + ws[2] + ws[3]) * (1.0f / CMODEL);
    v0 -= mean; v1 -= mean; v2 -= mean; v3 -= mean;
    float q = v0 * v0 + v1 * v1 + v2 * v2 + v3 * v3;
#pragma unroll
    for (int o = 16; o > 0; o >>= 1) q += __shfl_xor_sync(0xffffffffu, q, o);
    __syncthreads();
    if ((t & 31) == 0) ws[t >> 5] = q;
    __syncthreads();
    const float var = (ws[0] + ws[1] + ws[2] + ws[3]) * (1.0f / CMODEL);
    const float rs = rsqrtf(var + LNEPS);
    float4 gg = ((const float4*)g)[t], bb = ((const float4*)be)[t];
    float4 out;
    out.x = v0 * rs * gg.x + bb.x;
    out.y = v1 * rs * gg.y + bb.y;
    out.z = v2 * rs * gg.z + bb.z;
    out.w = v3 * rs * gg.w + bb.w;
    ((float4*)(O + (size_t)row * CMODEL))[t] = out;
}

// ---------------- host orchestration ----------------
extern "C" void kernel_launch(void* const* d_in, const int* in_sizes, int n_in,
                              void* d_out, int out_size)
{
    (void)in_sizes; (void)n_in; (void)out_size;
    const float* x      = (const float*)d_in[0];
    const float* qkv_w  = (const float*)d_in[1];
    const float* qkv_b  = (const float*)d_in[2];
    const float* out_w  = (const float*)d_in[3];
    const float* out_b  = (const float*)d_in[4];
    const float* ffn_w1 = (const float*)d_in[5];
    const float* ffn_b1 = (const float*)d_in[6];
    const float* ffn_w2 = (const float*)d_in[7];
    const float* ffn_b2 = (const float*)d_in[8];
    const float* n1_g   = (const float*)d_in[9];
    const float* n1_b   = (const float*)d_in[10];
    const float* n2_g   = (const float*)d_in[11];
    const float* n2_b   = (const float*)d_in[12];
    const float* conv_w = (const float*)d_in[13];
    const float* conv_b = (const float*)d_in[14];
    const float* cn_g   = (const float*)d_in[15];
    const float* cn_b   = (const float*)d_in[16];
    float* out = (float*)d_out;

    float *p_qkv, *p_hff, *p_attnO, *p_t1, *p_x1, *p_x2, *p_cy, *p_wr;
    __nv_bfloat16 *p_ah, *p_al, *p_bh, *p_bl;
    cudaGetSymbolAddress((void**)&p_qkv,   g_qkv);
    cudaGetSymbolAddress((void**)&p_hff,   g_hff);
    cudaGetSymbolAddress((void**)&p_attnO, g_attnO);
    cudaGetSymbolAddress((void**)&p_t1,    g_t1);
    cudaGetSymbolAddress((void**)&p_x1,    g_x1);
    cudaGetSymbolAddress((void**)&p_x2,    g_x2);
    cudaGetSymbolAddress((void**)&p_cy,    g_cy);
    cudaGetSymbolAddress((void**)&p_wr,    g_wr);
    cudaGetSymbolAddress((void**)&p_ah,    g_ah);
    cudaGetSymbolAddress((void**)&p_al,    g_al);
    cudaGetSymbolAddress((void**)&p_bh,    g_bh);
    cudaGetSymbolAddress((void**)&p_bl,    g_bl);

    cudaFuncSetAttribute(k_hgemm,  cudaFuncAttributeMaxDynamicSharedMemorySize, HG_SMEM);
    cudaFuncSetAttribute(k_rowmax, cudaFuncAttributeMaxDynamicSharedMemorySize, RM_SMEM);

    // 1) QKV projection (scalar fp32 — selection-critical)
    k_sgemm<<<dim3(QKVC / 128, NTOK / 128), 256>>>(x, qkv_w, qkv_b, p_qkv, NTOK, QKVC, CMODEL, 0);
    // 2) stats, rowmax (Q-resident), top-k, attention
    k_kstats<<<BATCH * NHEADS, 256>>>();
    k_rowmax<<<dim3(SEQ / 128, BATCH * NHEADS), 256, RM_SMEM>>>();
    k_topk<<<BATCH * NHEADS, 1024>>>();
    k_fill<<<(NTOK * CMODEL) / 256, 256>>>();
    k_attn_sel<<<dim3(NTOP / 16, BATCH * NHEADS), 128>>>();
    // 3) output projection (pipelined split-bf16 mma) + LN1
    k_cvt<<<(NTOK * CMODEL) / 256, 256>>>(p_attnO, p_ah, p_al, NTOK * CMODEL);
    k_cvt<<<(CMODEL * CMODEL) / 256, 256>>>(out_w, p_bh, p_bl, CMODEL * CMODEL);
    k_hgemm<<<dim3(CMODEL / 128, NTOK / 128), 256, HG_SMEM>>>(p_ah, p_al, p_bh, p_bl, out_b, p_t1, NTOK, CMODEL, CMODEL, 0);
    k_addln<<<NTOK, 128>>>(x, p_t1, n1_g, n1_b, p_x1);
    // 4) FFN + LN2
    k_cvt<<<(NTOK * CMODEL) / 256, 256>>>(p_x1, p_ah, p_al, NTOK * CMODEL);
    k_cvt<<<(CMODEL * DFF) / 256, 256>>>(ffn_w1, p_bh, p_bl, CMODEL * DFF);
    k_hgemm<<<dim3(DFF / 128, NTOK / 128), 256, HG_SMEM>>>(p_ah, p_al, p_bh, p_bl, ffn_b1, p_hff, NTOK, DFF, CMODEL, 1);
    k_cvt<<<(NTOK * DFF) / 256, 256>>>(p_hff, p_ah, p_al, NTOK * DFF);
    k_cvt<<<(DFF * CMODEL) / 256, 256>>>(ffn_w2, p_bh, p_bl, DFF * CMODEL);
    k_hgemm<<<dim3(CMODEL / 128, NTOK / 128), 256, HG_SMEM>>>(p_ah, p_al, p_bh, p_bl, ffn_b2, p_t1, NTOK, CMODEL, DFF, 0);
    k_addln<<<NTOK, 128>>>(p_x1, p_t1, n2_g, n2_b, p_x2);
    // 5) circular conv1d(k=3): pack B [1536,512] fp32 -> split bf16, pack A with circular shift
    k_packW<<<(3 * CMODEL * CMODEL) / 256, 256>>>(conv_w);
    k_cvt<<<(3 * CMODEL * CMODEL) / 256, 256>>>(p_wr, p_bh, p_bl, 3 * CMODEL * CMODEL);
    k_packXcvt<<<(NTOK * QKVC) / 256, 256>>>();
    k_hgemm<<<dim3(CMODEL / 128, NTOK / 128), 256, HG_SMEM>>>(p_ah, p_al, p_bh, p_bl, conv_b, p_cy, NTOK, CMODEL, QKVC, 0);
    // 6) maxpool + ELU + LN -> d_out
    k_poolln<<<BATCH * (SEQ / 2), 128>>>(p_cy, cn_g, cn_b, out);
}

// round 15
// speedup vs baseline: 2.8603x; 1.1803x over previous
#include <cuda_runtime.h>
#include <cuda_bf16.h>
#include <math.h>
#include <stdint.h>

#define BATCH   2
#define SEQ     2048
#define CMODEL  512
#define NHEADS  8
#define DK      64
#define DFF     2048
#define QKVC    1536
#define NTOK    (BATCH*SEQ)     /* 4096 */
#define NTOP    512
#define SCALE   0.125f
#define LNEPS   1e-5f
#define NEGINF  -3.402823466e38f

// ---------------- scratch (static device globals; no allocation) ----------------
__device__ float g_qkv[NTOK*QKVC];
__device__ float g_t1[NTOK*CMODEL];
__device__ float g_x1[NTOK*CMODEL];
__device__ float g_x2[NTOK*CMODEL];
__device__ float g_cy[NTOK*CMODEL];
__device__ float g_rowmax[BATCH*NHEADS*SEQ];
__device__ float g_M[BATCH*NHEADS*SEQ];
__device__ float g_ksum[BATCH*NHEADS*DK];
__device__ float g_vmean[BATCH*NHEADS*DK];
__device__ int   g_topidx[BATCH*NHEADS*NTOP];
// split-bf16 operands
__device__ __nv_bfloat16 g_ah[NTOK*QKVC];     // A operand hi (attnO / x1 / packed conv X)
__device__ __nv_bfloat16 g_al[NTOK*QKVC];     // A operand lo
__device__ __nv_bfloat16 g_a2h[NTOK*DFF];     // FFN1 output hi (FFN2 A operand)
__device__ __nv_bfloat16 g_a2l[NTOK*DFF];     // FFN1 output lo
__device__ __nv_bfloat16 g_bh[DFF*CMODEL];    // B operand hi
__device__ __nv_bfloat16 g_bl[DFF*CMODEL];    // B operand lo

// ---------------- small PTX helpers ----------------
__device__ __forceinline__ uint32_t smem_u32(const void* p) {
    return (uint32_t)__cvta_generic_to_shared(p);
}
__device__ __forceinline__ void cpa16(void* dst, const void* src) {
    asm volatile("cp.async.cg.shared.global [%0], [%1], 16;"
                 :: "r"(smem_u32(dst)), "l"(src));
}
__device__ __forceinline__ void mma16816(float* c, const unsigned* a, const unsigned* b) {
    asm volatile(
        "mma.sync.aligned.m16n8k16.row.col.f32.bf16.bf16.f32 "
        "{%0,%1,%2,%3}, {%4,%5,%6,%7}, {%8,%9}, {%0,%1,%2,%3};"
        : "+f"(c[0]), "+f"(c[1]), "+f"(c[2]), "+f"(c[3])
        : "r"(a[0]), "r"(a[1]), "r"(a[2]), "r"(a[3]), "r"(b[0]), "r"(b[1]));
}
__device__ __forceinline__ void ldsm4(unsigned* r, const void* p) {
    asm volatile("ldmatrix.sync.aligned.m8n8.x4.shared.b16 {%0,%1,%2,%3}, [%4];"
                 : "=r"(r[0]), "=r"(r[1]), "=r"(r[2]), "=r"(r[3]) : "r"(smem_u32(p)));
}
__device__ __forceinline__ void ldsm4t(unsigned* r, const void* p) {
    asm volatile("ldmatrix.sync.aligned.m8n8.x4.trans.shared.b16 {%0,%1,%2,%3}, [%4];"
                 : "=r"(r[0]), "=r"(r[1]), "=r"(r[2]), "=r"(r[3]) : "r"(smem_u32(p)));
}
__device__ __forceinline__ void split32(float x, __nv_bfloat16& h, __nv_bfloat16& l) {
    h = __float2bfloat16_rn(x);
    l = __float2bfloat16_rn(x - __bfloat162float(h));
}

// ---------------- pipelined split-bf16 tensor GEMM ----------------
#define AP 40
#define BP 136
#define ST_BYTES 37888
#define SO_AH 0
#define SO_AL 10240
#define SO_BH 20480
#define SO_BL 29184
#define HG_SMEM (2*ST_BYTES)

__global__ __launch_bounds__(256) void k_hgemm(
    const __nv_bfloat16* __restrict__ Agh, const __nv_bfloat16* __restrict__ Agl,
    const __nv_bfloat16* __restrict__ Bgh, const __nv_bfloat16* __restrict__ Bgl,
    const float* __restrict__ bias, float* __restrict__ C,
    __nv_bfloat16* __restrict__ Ch, __nv_bfloat16* __restrict__ Cl,
    int M, int N, int K, int gelu, int osplit)
{
    extern __shared__ __align__(16) char sm_[];
    const int t = threadIdx.x;
    const int warp = t >> 5, lane = t & 31;
    const int wm = warp >> 1, wn = warp & 1;
    const int bm = blockIdx.y * 128, bn = blockIdx.x * 128;

    float acc[2][8][4];
#pragma unroll
    for (int i = 0; i < 2; i++)
#pragma unroll
        for (int j = 0; j < 8; j++)
#pragma unroll
            for (int q = 0; q < 4; q++) acc[i][j][q] = 0.f;

    const int ar0 = t >> 2, ac0 = (t & 3) * 8;
    const int br0 = t >> 4, bc0 = (t & 15) * 8;
    const int nch = K >> 5;

    auto load = [&](int s, int c) {
        char* sp = sm_ + s * ST_BYTES;
        const int k0 = c << 5;
#pragma unroll
        for (int i = 0; i < 2; i++) {
            const int r = ar0 + i * 64;
            cpa16(sp + SO_AH + (r * AP + ac0) * 2, Agh + (size_t)(bm + r) * K + k0 + ac0);
            cpa16(sp + SO_AL + (r * AP + ac0) * 2, Agl + (size_t)(bm + r) * K + k0 + ac0);
        }
#pragma unroll
        for (int i = 0; i < 2; i++) {
            const int r = br0 + i * 16;
            cpa16(sp + SO_BH + (r * BP + bc0) * 2, Bgh + (size_t)(k0 + r) * N + bn + bc0);
            cpa16(sp + SO_BL + (r * BP + bc0) * 2, Bgl + (size_t)(k0 + r) * N + bn + bc0);
        }
        asm volatile("cp.async.commit_group;" ::: "memory");
    };

    load(0, 0);
    for (int c = 0; c < nch; c++) {
        if (c + 1 < nch) {
            load((c + 1) & 1, c + 1);
            asm volatile("cp.async.wait_group 1;" ::: "memory");
        } else {
            asm volatile("cp.async.wait_group 0;" ::: "memory");
        }
        __syncthreads();

        char* sp = sm_ + (c & 1) * ST_BYTES;
        const __nv_bfloat16 (*Ah)[AP] = (const __nv_bfloat16 (*)[AP])(sp + SO_AH);
        const __nv_bfloat16 (*Al)[AP] = (const __nv_bfloat16 (*)[AP])(sp + SO_AL);
        const __nv_bfloat16 (*Bh)[BP] = (const __nv_bfloat16 (*)[BP])(sp + SO_BH);
        const __nv_bfloat16 (*Bl)[BP] = (const __nv_bfloat16 (*)[BP])(sp + SO_BL);

#pragma unroll
        for (int ks = 0; ks < 32; ks += 16) {
            unsigned ah[2][4], al[2][4];
#pragma unroll
            for (int mt = 0; mt < 2; mt++) {
                const int r = wm * 32 + mt * 16 + (lane & 15);
                const int cc = ks + (lane >> 4) * 8;
                ldsm4(ah[mt], &Ah[r][cc]);
                ldsm4(al[mt], &Al[r][cc]);
            }
#pragma unroll
            for (int np = 0; np < 4; np++) {
                unsigned bh[4], bl[4];
                const int r = ks + (lane & 15);
                const int cc = wn * 64 + np * 16 + (lane >> 4) * 8;
                ldsm4t(bh, &Bh[r][cc]);
                ldsm4t(bl, &Bl[r][cc]);
#pragma unroll
                for (int mt = 0; mt < 2; mt++) {
                    mma16816(acc[mt][2 * np],     ah[mt], bh);
                    mma16816(acc[mt][2 * np],     ah[mt], bl);
                    mma16816(acc[mt][2 * np],     al[mt], bh);
                    mma16816(acc[mt][2 * np + 1], ah[mt], bh + 2);
                    mma16816(acc[mt][2 * np + 1], ah[mt], bl + 2);
                    mma16816(acc[mt][2 * np + 1], al[mt], bh + 2);
                }
            }
        }
        __syncthreads();
    }

    const int g = lane >> 2, tg = lane & 3;
#pragma unroll
    for (int mt = 0; mt < 2; mt++) {
#pragma unroll
        for (int nt = 0; nt < 8; nt++) {
            const int col = bn + wn * 64 + nt * 8 + 2 * tg;
            const float b0 = bias[col], b1 = bias[col + 1];
#pragma unroll
            for (int hrow = 0; hrow < 2; hrow++) {
                const int row = bm + wm * 32 + mt * 16 + g + hrow * 8;
                float v0 = acc[mt][nt][2 * hrow]     + b0;
                float v1 = acc[mt][nt][2 * hrow + 1] + b1;
                if (gelu) {
                    v0 = 0.5f * v0 * (1.0f + erff(v0 * 0.70710678118654752f));
                    v1 = 0.5f * v1 * (1.0f + erff(v1 * 0.70710678118654752f));
                }
                if (osplit) {
                    __nv_bfloat16 h0, l0, h1, l1;
                    split32(v0, h0, l0);
                    split32(v1, h1, l1);
                    __nv_bfloat162 hv; hv.x = h0; hv.y = h1;
                    __nv_bfloat162 lv; lv.x = l0; lv.y = l1;
                    *(__nv_bfloat162*)(Ch + (size_t)row * N + col) = hv;
                    *(__nv_bfloat162*)(Cl + (size_t)row * N + col) = lv;
                } else {
                    *(float2*)(C + (size_t)row * N + col) = make_float2(v0, v1);
                }
            }
        }
    }
}

// ---------------- fp32 -> (hi,lo) bf16 split (for weights) ----------------
__global__ __launch_bounds__(256) void k_cvt(
    const float* __restrict__ s, __nv_bfloat16* __restrict__ hi,
    __nv_bfloat16* __restrict__ lo, int n)
{
    const int i = blockIdx.x * 256 + threadIdx.x;
    if (i < n) {
        __nv_bfloat16 h, l;
        split32(s[i], h, l);
        hi[i] = h; lo[i] = l;
    }
}

// ---------------- scalar fp32 SGEMM, reg-prefetch pipelined (QKV) ----------------
__global__ __launch_bounds__(256) void k_sgemm(
    const float* __restrict__ A, const float* __restrict__ B,
    const float* __restrict__ bias, float* __restrict__ C,
    int M, int N, int K)
{
    __shared__ float As[16][128];
    __shared__ float Bs[16][128];
    const int bm = blockIdx.y * 128;
    const int bn = blockIdx.x * 128;
    const int t  = threadIdx.x;
    const int tx = t & 15, ty = t >> 4;

    float acc[8][8];
#pragma unroll
    for (int i = 0; i < 8; i++)
#pragma unroll
        for (int j = 0; j < 8; j++) acc[i][j] = 0.0f;

    const int arow = t >> 1, acol = (t & 1) * 8;
    const int brow = t >> 4, bcol = (t & 15) * 8;
    const float* Ap = A + (size_t)(bm + arow) * K + acol;
    const float* Bp = B + (size_t)brow * N + bn + bcol;

    float4 pa0 = *(const float4*)(Ap);
    float4 pa1 = *(const float4*)(Ap + 4);
    float4 pb0 = *(const float4*)(Bp);
    float4 pb1 = *(const float4*)(Bp + 4);

    for (int k0 = 0; k0 < K; k0 += 16) {
        As[acol + 0][arow] = pa0.x; As[acol + 1][arow] = pa0.y;
        As[acol + 2][arow] = pa0.z; As[acol + 3][arow] = pa0.w;
        As[acol + 4][arow] = pa1.x; As[acol + 5][arow] = pa1.y;
        As[acol + 6][arow] = pa1.z; As[acol + 7][arow] = pa1.w;
        *(float4*)&Bs[brow][bcol]     = pb0;
        *(float4*)&Bs[brow][bcol + 4] = pb1;
        __syncthreads();
        if (k0 + 16 < K) {
            pa0 = *(const float4*)(Ap + k0 + 16);
            pa1 = *(const float4*)(Ap + k0 + 20);
            pb0 = *(const float4*)(Bp + (size_t)(k0 + 16) * N);
            pb1 = *(const float4*)(Bp + (size_t)(k0 + 16) * N + 4);
        }
#pragma unroll
        for (int kk = 0; kk < 16; kk++) {
            float a[8], b[8];
            *(float4*)(a)     = *(float4*)&As[kk][ty * 8];
            *(float4*)(a + 4) = *(float4*)&As[kk][ty * 8 + 4];
            *(float4*)(b)     = *(float4*)&Bs[kk][tx * 8];
            *(float4*)(b + 4) = *(float4*)&Bs[kk][tx * 8 + 4];
#pragma unroll
            for (int i = 0; i < 8; i++)
#pragma unroll
                for (int j = 0; j < 8; j++) acc[i][j] += a[i] * b[j];
        }
        __syncthreads();
    }

#pragma unroll
    for (int i = 0; i < 8; i++) {
        const int row = bm + ty * 8 + i;
#pragma unroll
        for (int j = 0; j < 8; j++) {
            C[(size_t)row * N + bn + tx * 8 + j] = acc[i][j] + bias[bn + tx * 8 + j];
        }
    }
}

// ---------------- per-(b,h) ksum / vmean ----------------
__global__ __launch_bounds__(256) void k_kstats()
{
    const int bh = blockIdx.x, b = bh >> 3, h = bh & 7;
    const int t = threadIdx.x;
    const int d = t & 63, c = t >> 6;
    float ks = 0.f, vs = 0.f;
    for (int n = c * 512; n < (c + 1) * 512; n++) {
        const float* p = g_qkv + (size_t)(b * SEQ + n) * QKVC + CMODEL + h * DK + d;
        ks += p[0];
        vs += p[CMODEL];
    }
    __shared__ float sk[256], sv[256];
    sk[t] = ks; sv[t] = vs;
    __syncthreads();
    if (t < 64) {
        float a = sk[t] + sk[t + 64] + sk[t + 128] + sk[t + 192];
        float v = sv[t] + sv[t + 64] + sv[t + 128] + sv[t + 192];
        g_ksum[bh * DK + t]  = a;
        g_vmean[bh * DK + t] = v * (1.0f / SEQ);
    }
}

// ---------------- streamed QK^T row-max + M: Q preloaded, 64-deep K tiles ----------------
#define RM_SMEM ((2*64*128 + 128*17 + 64) * 4)
__global__ __launch_bounds__(256) void k_rowmax()
{
    extern __shared__ float rs_[];
    float (*Qs)[128] = (float (*)[128])rs_;
    float (*Ks)[128] = (float (*)[128])(rs_ + 64 * 128);
    float (*red)[17] = (float (*)[17])(rs_ + 2 * 64 * 128);
    float* ks = rs_ + 2 * 64 * 128 + 128 * 17;

    const int bh = blockIdx.y, b = bh >> 3, h = bh & 7;
    const int bm = blockIdx.x * 128;
    const int t = threadIdx.x;
    const int tx = t & 15, ty = t >> 4;
    const int arow = t >> 1, acol = (t & 1) * 4;

    const float* qbase = g_qkv + (size_t)(b * SEQ) * QKVC + h * DK;
    const float* kbase = qbase + CMODEL;

    if (t < 64) ks[t] = g_ksum[bh * DK + t];
#pragma unroll
    for (int k0 = 0; k0 < DK; k0 += 8) {
        float4 av = *(const float4*)(qbase + (size_t)(bm + arow) * QKVC + k0 + acol);
        Qs[k0 + acol + 0][arow] = av.x; Qs[k0 + acol + 1][arow] = av.y;
        Qs[k0 + acol + 2][arow] = av.z; Qs[k0 + acol + 3][arow] = av.w;
    }

    float lmax[8];
#pragma unroll
    for (int i = 0; i < 8; i++) lmax[i] = NEGINF;

    for (int m0 = 0; m0 < SEQ; m0 += 128) {
        __syncthreads();
#pragma unroll
        for (int k0 = 0; k0 < DK; k0 += 8) {
            float4 bv = *(const float4*)(kbase + (size_t)(m0 + arow) * QKVC + k0 + acol);
            Ks[k0 + acol + 0][arow] = bv.x; Ks[k0 + acol + 1][arow] = bv.y;
            Ks[k0 + acol + 2][arow] = bv.z; Ks[k0 + acol + 3][arow] = bv.w;
        }
        __syncthreads();

        float acc[8][8];
#pragma unroll
        for (int i = 0; i < 8; i++)
#pragma unroll
            for (int j = 0; j < 8; j++) acc[i][j] = 0.0f;

#pragma unroll 8
        for (int kk = 0; kk < DK; kk++) {
            float a[8], bb[8];
            *(float4*)(a)      = *(float4*)&Qs[kk][ty * 8];
            *(float4*)(a + 4)  = *(float4*)&Qs[kk][ty * 8 + 4];
            *(float4*)(bb)     = *(float4*)&Ks[kk][tx * 8];
            *(float4*)(bb + 4) = *(float4*)&Ks[kk][tx * 8 + 4];
#pragma unroll
            for (int i = 0; i < 8; i++)
#pragma unroll
                for (int j = 0; j < 8; j++) acc[i][j] += a[i] * bb[j];
        }
#pragma unroll
        for (int i = 0; i < 8; i++) {
            float mx = acc[i][0];
#pragma unroll
            for (int j = 1; j < 8; j++) mx = fmaxf(mx, acc[i][j]);
            lmax[i] = fmaxf(lmax[i], mx);
        }
    }

    __syncthreads();
#pragma unroll
    for (int i = 0; i < 8; i++) red[ty * 8 + i][tx] = lmax[i];
    __syncthreads();
    if (t < 128) {
        float mx = red[t][0];
#pragma unroll
        for (int j = 1; j < 16; j++) mx = fmaxf(mx, red[t][j]);
        float qd = 0.f;
        const float* qp = qbase + (size_t)(bm + t) * QKVC;
#pragma unroll 8
        for (int d = 0; d < 64; d++) qd += qp[d] * ks[d];
        g_rowmax[bh * SEQ + bm + t] = SCALE * mx;
        g_M[bh * SEQ + bm + t]      = SCALE * mx - SCALE * qd * (1.0f / SEQ);
    }
}

// ---------------- exact top-512 per (b,h): in-smem bitonic sort ----------------
__global__ __launch_bounds__(1024) void k_topk()
{
    const int bh = blockIdx.x;
    const int t = threadIdx.x;
    __shared__ float sv[2048];
    __shared__ int   si[2048];
    sv[t]        = g_M[bh * SEQ + t];        si[t]        = t;
    sv[t + 1024] = g_M[bh * SEQ + t + 1024]; si[t + 1024] = t + 1024;

    for (int k = 2; k <= 2048; k <<= 1) {
        for (int j = k >> 1; j > 0; j >>= 1) {
            __syncthreads();
#pragma unroll 1
            for (int e = t; e < 2048; e += 1024) {
                const int p = e ^ j;
                if (p > e) {
                    float va = sv[e], vb = sv[p];
                    int   ia = si[e], ib = si[p];
                    bool gtr = (va > vb) || (va == vb && ia < ib);
                    bool desc = ((e & k) == 0);
                    if (desc ? !gtr : gtr) {
                        sv[e] = vb; sv[p] = va;
                        si[e] = ib; si[p] = ia;
                    }
                }
            }
        }
    }
    __syncthreads();
    if (t < NTOP) g_topidx[bh * NTOP + t] = si[t];
}

// ---------------- fill all rows with split(vmean) ----------------
__global__ __launch_bounds__(256) void k_fillsplit()
{
    const int i = blockIdx.x * 256 + threadIdx.x;
    const int c = i & 511;
    const int tok = i >> 9;
    const int b = tok >> 11;
    float v = g_vmean[(b * NHEADS + (c >> 6)) * DK + (c & 63)];
    __nv_bfloat16 h, l;
    split32(v, h, l);
    g_ah[i] = h; g_al[i] = l;
}

// ---------------- softmax @ V for selected rows: 32 rows/block, 256 thr ----------------
__global__ __launch_bounds__(256) void k_attn_sel()
{
    const int bh = blockIdx.y, b = bh >> 3, h = bh & 7;
    const int t = threadIdx.x;

    __shared__ float Qs[32][65];
    __shared__ float Ks[32][65];
    __shared__ float Vs[32][65];
    __shared__ float Se[32][33];
    __shared__ float sume[32];
    __shared__ float rmax[32];
    __shared__ int   nidx[32];

    if (t < 32) {
        int n = g_topidx[bh * NTOP + blockIdx.x * 32 + t];
        nidx[t] = n;
        sume[t] = 0.f;
        rmax[t] = g_rowmax[bh * SEQ + n];
    }
    __syncthreads();

    // load 32 Q rows (32 x 64): 512 float4 loads, scalar smem stores (65-pad alignment)
#pragma unroll
    for (int i = 0; i < 2; i++) {
        const int idx = i * 256 + t;
        const int qr = idx >> 4, cc = (idx & 15) * 4;
        const float* qp = g_qkv + (size_t)(b * SEQ + nidx[qr]) * QKVC + h * DK + cc;
        float4 v = *(const float4*)qp;
        Qs[qr][cc + 0] = v.x; Qs[qr][cc + 1] = v.y;
        Qs[qr][cc + 2] = v.z; Qs[qr][cc + 3] = v.w;
    }

    const int r  = t >> 3;        // row 0..31
    const int mg = (t & 7) * 4;   // 4 score cols
    const int dg = (t & 7) * 8;   // 8 out dims
    const float rm = rmax[r];

    float o[8];
#pragma unroll
    for (int i = 0; i < 8; i++) o[i] = 0.f;

    for (int m0 = 0; m0 < SEQ; m0 += 32) {
        __syncthreads();
#pragma unroll
        for (int i = 0; i < 2; i++) {
            const int idx = i * 256 + t;
            const int mr = idx >> 4, cc = (idx & 15) * 4;
            const float* kp = g_qkv + (size_t)(b * SEQ + m0 + mr) * QKVC + CMODEL + h * DK + cc;
            float4 kv = *(const float4*)kp;
            float4 vv = *(const float4*)(kp + CMODEL);
            Ks[mr][cc + 0] = kv.x; Ks[mr][cc + 1] = kv.y;
            Ks[mr][cc + 2] = kv.z; Ks[mr][cc + 3] = kv.w;
            Vs[mr][cc + 0] = vv.x; Vs[mr][cc + 1] = vv.y;
            Vs[mr][cc + 2] = vv.z; Vs[mr][cc + 3] = vv.w;
        }
        __syncthreads();

        float s[4];
#pragma unroll
        for (int j = 0; j < 4; j++) s[j] = 0.f;
#pragma unroll 8
        for (int d = 0; d < 64; d++) {
            const float qv = Qs[r][d];
#pragma unroll
            for (int j = 0; j < 4; j++) s[j] += qv * Ks[mg + j][d];
        }
        float lsum = 0.f;
#pragma unroll
        for (int j = 0; j < 4; j++) {
            float ev = __expf(s[j] * SCALE - rm);
            Se[r][mg + j] = ev;
            lsum += ev;
        }
        atomicAdd(&sume[r], lsum);
        __syncthreads();

#pragma unroll 8
        for (int m = 0; m < 32; m++) {
            const float ev = Se[r][m];
#pragma unroll
            for (int i = 0; i < 8; i++) o[i] += ev * Vs[m][dg + i];
        }
    }
    __syncthreads();
    const float inv = 1.0f / sume[r];
    const size_t base = (size_t)(b * SEQ + nidx[r]) * CMODEL + h * DK + dg;
#pragma unroll
    for (int i = 0; i < 8; i++) {
        __nv_bfloat16 hh, ll;
        split32(o[i] * inv, hh, ll);
        g_ah[base + i] = hh;
        g_al[base + i] = ll;
    }
}

// ---------------- fused residual add + LayerNorm (+ optional split output) ----------------
__global__ __launch_bounds__(128) void k_addln(
    const float* __restrict__ A, const float* __restrict__ Bv,
    const float* __restrict__ g, const float* __restrict__ be, float* __restrict__ O,
    __nv_bfloat16* __restrict__ Oh, __nv_bfloat16* __restrict__ Ol)
{
    const int row = blockIdx.x, t = threadIdx.x;
    float4 a = ((const float4*)(A  + (size_t)row * CMODEL))[t];
    float4 b = ((const float4*)(Bv + (size_t)row * CMODEL))[t];
    float v0 = a.x + b.x, v1 = a.y + b.y, v2 = a.z + b.z, v3 = a.w + b.w;

    __shared__ float ws[4];
    float s = v0 + v1 + v2 + v3;
#pragma unroll
    for (int o = 16; o > 0; o >>= 1) s += __shfl_xor_sync(0xffffffffu, s, o);
    if ((t & 31) == 0) ws[t >> 5] = s;
    __syncthreads();
    const float mean = (ws[0] + ws[1] + ws[2] + ws[3]) * (1.0f / CMODEL);
    v0 -= mean; v1 -= mean; v2 -= mean; v3 -= mean;
    float q = v0 * v0 + v1 * v1 + v2 * v2 + v3 * v3;
#pragma unroll
    for (int o = 16; o > 0; o >>= 1) q += __shfl_xor_sync(0xffffffffu, q, o);
    __syncthreads();
    if ((t & 31) == 0) ws[t >> 5] = q;
    __syncthreads();
    const float var = (ws[0] + ws[1] + ws[2] + ws[3]) * (1.0f / CMODEL);
    const float rs = rsqrtf(var + LNEPS);
    float4 gg = ((const float4*)g)[t], bb = ((const float4*)be)[t];
    float4 out;
    out.x = v0 * rs * gg.x + bb.x;
    out.y = v1 * rs * gg.y + bb.y;
    out.z = v2 * rs * gg.z + bb.z;
    out.w = v3 * rs * gg.w + bb.w;
    ((float4*)(O + (size_t)row * CMODEL))[t] = out;
    if (Oh) {
        const size_t base = (size_t)row * CMODEL + t * 4;
        __nv_bfloat16 h0, l0, h1, l1, h2, l2, h3, l3;
        split32(out.x, h0, l0); split32(out.y, h1, l1);
        split32(out.z, h2, l2); split32(out.w, h3, l3);
        __nv_bfloat162 ha; ha.x = h0; ha.y = h1;
        __nv_bfloat162 hb; hb.x = h2; hb.y = h3;
        __nv_bfloat162 la; la.x = l0; la.y = l1;
        __nv_bfloat162 lb; lb.x = l2; lb.y = l3;
        *(__nv_bfloat162*)(Oh + base)     = ha;
        *(__nv_bfloat162*)(Oh + base + 2) = hb;
        *(__nv_bfloat162*)(Ol + base)     = la;
        *(__nv_bfloat162*)(Ol + base + 2) = lb;
    }
}

// ---------------- conv weight: pack + split in one pass ----------------
__global__ __launch_bounds__(256) void k_packWcvt(const float* __restrict__ w)
{
    const int i = blockIdx.x * 256 + threadIdx.x;   // over 1536*512
    const int co = i & 511;
    const int rr = i >> 9;
    const int ci = rr & 511;
    const int k  = rr >> 9;
    __nv_bfloat16 h, l;
    split32(w[(co * CMODEL + ci) * 3 + k], h, l);
    g_bh[i] = h; g_bl[i] = l;
}

// ---------------- circular-shift pack of x2 -> split bf16 A [4096,1536] ----------------
__global__ __launch_bounds__(256) void k_packXcvt()
{
    const int i = blockIdx.x * 256 + threadIdx.x;
    const int col = i % QKVC, tok = i / QKVC;
    const int b = tok >> 11, n = tok & 2047;
    const int k = col >> 9, ci = col & 511;
    const int ns = (n - 1 + k + SEQ) & (SEQ - 1);
    __nv_bfloat16 h, l;
    split32(g_x2[(size_t)(b * SEQ + ns) * CMODEL + ci], h, l);
    g_ah[i] = h; g_al[i] = l;
}

// ---------------- maxpool + ELU + LayerNorm -> final output ----------------
__global__ __launch_bounds__(128) void k_poolln(
    const float* __restrict__ Y, const float* __restrict__ g,
    const float* __restrict__ be, float* __restrict__ O)
{
    const int row = blockIdx.x;
    const int b = row >> 10, j = row & 1023;
    const int t = threadIdx.x;
    const int c = t * 4;

    float m0 = NEGINF, m1 = NEGINF, m2 = NEGINF, m3 = NEGINF;
#pragma unroll
    for (int dn = 0; dn < 3; dn++) {
        const int n = 2 * j - 1 + dn;
        if (n >= 0 && n < SEQ) {
            float4 w = *(const float4*)(Y + (size_t)(b * SEQ + n) * CMODEL + c);
            m0 = fmaxf(m0, w.x); m1 = fmaxf(m1, w.y);
            m2 = fmaxf(m2, w.z); m3 = fmaxf(m3, w.w);
        }
    }
    float v0 = m0 > 0.f ? m0 : expm1f(m0);
    float v1 = m1 > 0.f ? m1 : expm1f(m1);
    float v2 = m2 > 0.f ? m2 : expm1f(m2);
    float v3 = m3 > 0.f ? m3 : expm1f(m3);

    __shared__ float ws[4];
    float s = v0 + v1 + v2 + v3;
#pragma unroll
    for (int o = 16; o > 0; o >>= 1) s += __shfl_xor_sync(0xffffffffu, s, o);
    if ((t & 31) == 0) ws[t >> 5] = s;
    __syncthreads();
    const float mean = (ws[0] + ws[1] + ws[2] + ws[3]) * (1.0f / CMODEL);
    v0 -= mean; v1 -= mean; v2 -= mean; v3 -= mean;
    float q = v0 * v0 + v1 * v1 + v2 * v2 + v3 * v3;
#pragma unroll
    for (int o = 16; o > 0; o >>= 1) q += __shfl_xor_sync(0xffffffffu, q, o);
    __syncthreads();
    if ((t & 31) == 0) ws[t >> 5] = q;
    __syncthreads();
    const float var = (ws[0] + ws[1] + ws[2] + ws[3]) * (1.0f / CMODEL);
    const float rs = rsqrtf(var + LNEPS);
    float4 gg = ((const float4*)g)[t], bb = ((const float4*)be)[t];
    float4 out;
    out.x = v0 * rs * gg.x + bb.x;
    out.y = v1 * rs * gg.y + bb.y;
    out.z = v2 * rs * gg.z + bb.z;
    out.w = v3 * rs * gg.w + bb.w;
    ((float4*)(O + (size_t)row * CMODEL))[t] = out;
}

// ---------------- host orchestration ----------------
extern "C" void kernel_launch(void* const* d_in, const int* in_sizes, int n_in,
                              void* d_out, int out_size)
{
    (void)in_sizes; (void)n_in; (void)out_size;
    const float* x      = (const float*)d_in[0];
    const float* qkv_w  = (const float*)d_in[1];
    const float* qkv_b  = (const float*)d_in[2];
    const float* out_w  = (const float*)d_in[3];
    const float* out_b  = (const float*)d_in[4];
    const float* ffn_w1 = (const float*)d_in[5];
    const float* ffn_b1 = (const float*)d_in[6];
    const float* ffn_w2 = (const float*)d_in[7];
    const float* ffn_b2 = (const float*)d_in[8];
    const float* n1_g   = (const float*)d_in[9];
    const float* n1_b   = (const float*)d_in[10];
    const float* n2_g   = (const float*)d_in[11];
    const float* n2_b   = (const float*)d_in[12];
    const float* conv_w = (const float*)d_in[13];
    const float* conv_b = (const float*)d_in[14];
    const float* cn_g   = (const float*)d_in[15];
    const float* cn_b   = (const float*)d_in[16];
    float* out = (float*)d_out;

    float *p_qkv, *p_t1, *p_x1, *p_x2, *p_cy;
    __nv_bfloat16 *p_ah, *p_al, *p_a2h, *p_a2l, *p_bh, *p_bl;
    cudaGetSymbolAddress((void**)&p_qkv,  g_qkv);
    cudaGetSymbolAddress((void**)&p_t1,   g_t1);
    cudaGetSymbolAddress((void**)&p_x1,   g_x1);
    cudaGetSymbolAddress((void**)&p_x2,   g_x2);
    cudaGetSymbolAddress((void**)&p_cy,   g_cy);
    cudaGetSymbolAddress((void**)&p_ah,   g_ah);
    cudaGetSymbolAddress((void**)&p_al,   g_al);
    cudaGetSymbolAddress((void**)&p_a2h,  g_a2h);
    cudaGetSymbolAddress((void**)&p_a2l,  g_a2l);
    cudaGetSymbolAddress((void**)&p_bh,   g_bh);
    cudaGetSymbolAddress((void**)&p_bl,   g_bl);

    cudaFuncSetAttribute(k_hgemm,  cudaFuncAttributeMaxDynamicSharedMemorySize, HG_SMEM);
    cudaFuncSetAttribute(k_rowmax, cudaFuncAttributeMaxDynamicSharedMemorySize, RM_SMEM);

    // 1) QKV projection (pipelined scalar fp32 — selection-critical)
    k_sgemm<<<dim3(QKVC / 128, NTOK / 128), 256>>>(x, qkv_w, qkv_b, p_qkv, NTOK, QKVC, CMODEL);
    // 2) stats, rowmax, top-k, attention (attn writes split attnO directly)
    k_kstats<<<BATCH * NHEADS, 256>>>();
    k_rowmax<<<dim3(SEQ / 128, BATCH * NHEADS), 256, RM_SMEM>>>();
    k_topk<<<BATCH * NHEADS, 1024>>>();
    k_fillsplit<<<(NTOK * CMODEL) / 256, 256>>>();
    k_attn_sel<<<dim3(NTOP / 32, BATCH * NHEADS), 256>>>();
    // 3) output projection + LN1 (LN1 emits x1 fp32 + splits)
    k_cvt<<<(CMODEL * CMODEL) / 256, 256>>>(out_w, p_bh, p_bl, CMODEL * CMODEL);
    k_hgemm<<<dim3(CMODEL / 128, NTOK / 128), 256, HG_SMEM>>>(p_ah, p_al, p_bh, p_bl, out_b, p_t1, 0, 0, NTOK, CMODEL, CMODEL, 0, 0);
    k_addln<<<NTOK, 128>>>(x, p_t1, n1_g, n1_b, p_x1, p_ah, p_al);
    // 4) FFN (FFN1 emits split GELU output straight into FFN2's A operand) + LN2
    k_cvt<<<(CMODEL * DFF) / 256, 256>>>(ffn_w1, p_bh, p_bl, CMODEL * DFF);
    k_hgemm<<<dim3(DFF / 128, NTOK / 128), 256, HG_SMEM>>>(p_ah, p_al, p_bh, p_bl, ffn_b1, 0, p_a2h, p_a2l, NTOK, DFF, CMODEL, 1, 1);
    k_cvt<<<(DFF * CMODEL) / 256, 256>>>(ffn_w2, p_bh, p_bl, DFF * CMODEL);
    k_hgemm<<<dim3(CMODEL / 128, NTOK / 128), 256, HG_SMEM>>>(p_a2h, p_a2l, p_bh, p_bl, ffn_b2, p_t1, 0, 0, NTOK, CMODEL, DFF, 0, 0);
    k_addln<<<NTOK, 128>>>(p_x1, p_t1, n2_g, n2_b, p_x2, 0, 0);
    // 5) circular conv1d(k=3) as split-bf16 GEMM
    k_packWcvt<<<(QKVC * CMODEL) / 256, 256>>>(conv_w);
    k_packXcvt<<<(NTOK * QKVC) / 256, 256>>>();
    k_hgemm<<<dim3(CMODEL / 128, NTOK / 128), 256, HG_SMEM>>>(p_ah, p_al, p_bh, p_bl, conv_b, p_cy, 0, 0, NTOK, CMODEL, QKVC, 0, 0);
    // 6) maxpool + ELU + LN -> d_out
    k_poolln<<<BATCH * (SEQ / 2), 128>>>(p_cy, cn_g, cn_b, out);
}

// round 16
// speedup vs baseline: 2.9977x; 1.0480x over previous
#include <cuda_runtime.h>
#include <cuda_fp16.h>
#include <math.h>
#include <stdint.h>

#define BATCH   2
#define SEQ     2048
#define CMODEL  512
#define NHEADS  8
#define DK      64
#define DFF     2048
#define QKVC    1536
#define NTOK    (BATCH*SEQ)     /* 4096 */
#define NTOP    512
#define SCALE   0.125f
#define LNEPS   1e-5f
#define NEGINF  -3.402823466e38f

// ---------------- scratch (static device globals; no allocation) ----------------
__device__ float g_qkv[NTOK*QKVC];
__device__ float g_t1[NTOK*CMODEL];
__device__ float g_x1[NTOK*CMODEL];
__device__ float g_x2[NTOK*CMODEL];
__device__ float g_cy[NTOK*CMODEL];
__device__ float g_rowmax[BATCH*NHEADS*SEQ];
__device__ float g_M[BATCH*NHEADS*SEQ];
__device__ float g_ksum[BATCH*NHEADS*DK];
__device__ float g_vmean[BATCH*NHEADS*DK];
__device__ int   g_topidx[BATCH*NHEADS*NTOP];
// split-fp16 operands: A = hi+lo (exact to ~2^-22), B = hi only (~2^-12)
__device__ __half g_ah[NTOK*QKVC];     // A hi (attnO / x1 / packed conv X)
__device__ __half g_al[NTOK*QKVC];     // A lo
__device__ __half g_a2h[NTOK*DFF];     // FFN1 output hi (FFN2 A operand)
__device__ __half g_a2l[NTOK*DFF];     // FFN1 output lo
__device__ __half g_bh[DFF*CMODEL];    // B operand (fp16)

// ---------------- small PTX helpers ----------------
__device__ __forceinline__ uint32_t smem_u32(const void* p) {
    return (uint32_t)__cvta_generic_to_shared(p);
}
__device__ __forceinline__ void cpa16(void* dst, const void* src) {
    asm volatile("cp.async.cg.shared.global [%0], [%1], 16;"
                 :: "r"(smem_u32(dst)), "l"(src));
}
__device__ __forceinline__ void mma16816(float* c, const unsigned* a, const unsigned* b) {
    asm volatile(
        "mma.sync.aligned.m16n8k16.row.col.f32.f16.f16.f32 "
        "{%0,%1,%2,%3}, {%4,%5,%6,%7}, {%8,%9}, {%0,%1,%2,%3};"
        : "+f"(c[0]), "+f"(c[1]), "+f"(c[2]), "+f"(c[3])
        : "r"(a[0]), "r"(a[1]), "r"(a[2]), "r"(a[3]), "r"(b[0]), "r"(b[1]));
}
__device__ __forceinline__ void ldsm4(unsigned* r, const void* p) {
    asm volatile("ldmatrix.sync.aligned.m8n8.x4.shared.b16 {%0,%1,%2,%3}, [%4];"
                 : "=r"(r[0]), "=r"(r[1]), "=r"(r[2]), "=r"(r[3]) : "r"(smem_u32(p)));
}
__device__ __forceinline__ void ldsm4t(unsigned* r, const void* p) {
    asm volatile("ldmatrix.sync.aligned.m8n8.x4.trans.shared.b16 {%0,%1,%2,%3}, [%4];"
                 : "=r"(r[0]), "=r"(r[1]), "=r"(r[2]), "=r"(r[3]) : "r"(smem_u32(p)));
}
__device__ __forceinline__ void split16(float x, __half& h, __half& l) {
    h = __float2half_rn(x);
    l = __float2half_rn(x - __half2float(h));
}

// ---------------- pipelined 2-term fp16 tensor GEMM ----------------
// C[M,N] = (Ah+Al)@Bh + bias (opt exact GELU). BM=BN=128, BK=32, 2-stage cp.async.
#define AP 40
#define BP 136
#define ST_BYTES 29184          /* per-stage: A 2*10240 + B 8704 */
#define SO_AH 0
#define SO_AL 10240
#define SO_BH 20480
#define HG_SMEM (2*ST_BYTES)

__global__ __launch_bounds__(256) void k_hgemm(
    const __half* __restrict__ Agh, const __half* __restrict__ Agl,
    const __half* __restrict__ Bgh,
    const float* __restrict__ bias, float* __restrict__ C,
    __half* __restrict__ Ch, __half* __restrict__ Cl,
    int M, int N, int K, int gelu, int osplit)
{
    extern __shared__ __align__(16) char sm_[];
    const int t = threadIdx.x;
    const int warp = t >> 5, lane = t & 31;
    const int wm = warp >> 1, wn = warp & 1;
    const int bm = blockIdx.y * 128, bn = blockIdx.x * 128;

    float acc[2][8][4];
#pragma unroll
    for (int i = 0; i < 2; i++)
#pragma unroll
        for (int j = 0; j < 8; j++)
#pragma unroll
            for (int q = 0; q < 4; q++) acc[i][j][q] = 0.f;

    const int ar0 = t >> 2, ac0 = (t & 3) * 8;
    const int br0 = t >> 4, bc0 = (t & 15) * 8;
    const int nch = K >> 5;

    auto load = [&](int s, int c) {
        char* sp = sm_ + s * ST_BYTES;
        const int k0 = c << 5;
#pragma unroll
        for (int i = 0; i < 2; i++) {
            const int r = ar0 + i * 64;
            cpa16(sp + SO_AH + (r * AP + ac0) * 2, Agh + (size_t)(bm + r) * K + k0 + ac0);
            cpa16(sp + SO_AL + (r * AP + ac0) * 2, Agl + (size_t)(bm + r) * K + k0 + ac0);
        }
#pragma unroll
        for (int i = 0; i < 2; i++) {
            const int r = br0 + i * 16;
            cpa16(sp + SO_BH + (r * BP + bc0) * 2, Bgh + (size_t)(k0 + r) * N + bn + bc0);
        }
        asm volatile("cp.async.commit_group;" ::: "memory");
    };

    load(0, 0);
    for (int c = 0; c < nch; c++) {
        if (c + 1 < nch) {
            load((c + 1) & 1, c + 1);
            asm volatile("cp.async.wait_group 1;" ::: "memory");
        } else {
            asm volatile("cp.async.wait_group 0;" ::: "memory");
        }
        __syncthreads();

        char* sp = sm_ + (c & 1) * ST_BYTES;
        const __half (*Ah)[AP] = (const __half (*)[AP])(sp + SO_AH);
        const __half (*Al)[AP] = (const __half (*)[AP])(sp + SO_AL);
        const __half (*Bh)[BP] = (const __half (*)[BP])(sp + SO_BH);

#pragma unroll
        for (int ks = 0; ks < 32; ks += 16) {
            unsigned ah[2][4], al[2][4];
#pragma unroll
            for (int mt = 0; mt < 2; mt++) {
                const int r = wm * 32 + mt * 16 + (lane & 15);
                const int cc = ks + (lane >> 4) * 8;
                ldsm4(ah[mt], &Ah[r][cc]);
                ldsm4(al[mt], &Al[r][cc]);
            }
#pragma unroll
            for (int np = 0; np < 4; np++) {
                unsigned bh[4];
                const int r = ks + (lane & 15);
                const int cc = wn * 64 + np * 16 + (lane >> 4) * 8;
                ldsm4t(bh, &Bh[r][cc]);
#pragma unroll
                for (int mt = 0; mt < 2; mt++) {
                    mma16816(acc[mt][2 * np],     ah[mt], bh);
                    mma16816(acc[mt][2 * np],     al[mt], bh);
                    mma16816(acc[mt][2 * np + 1], ah[mt], bh + 2);
                    mma16816(acc[mt][2 * np + 1], al[mt], bh + 2);
                }
            }
        }
        __syncthreads();
    }

    const int g = lane >> 2, tg = lane & 3;
#pragma unroll
    for (int mt = 0; mt < 2; mt++) {
#pragma unroll
        for (int nt = 0; nt < 8; nt++) {
            const int col = bn + wn * 64 + nt * 8 + 2 * tg;
            const float b0 = bias[col], b1 = bias[col + 1];
#pragma unroll
            for (int hrow = 0; hrow < 2; hrow++) {
                const int row = bm + wm * 32 + mt * 16 + g + hrow * 8;
                float v0 = acc[mt][nt][2 * hrow]     + b0;
                float v1 = acc[mt][nt][2 * hrow + 1] + b1;
                if (gelu) {
                    v0 = 0.5f * v0 * (1.0f + erff(v0 * 0.70710678118654752f));
                    v1 = 0.5f * v1 * (1.0f + erff(v1 * 0.70710678118654752f));
                }
                if (osplit) {
                    __half h0, l0, h1, l1;
                    split16(v0, h0, l0);
                    split16(v1, h1, l1);
                    __half2 hv; hv.x = h0; hv.y = h1;
                    __half2 lv; lv.x = l0; lv.y = l1;
                    *(__half2*)(Ch + (size_t)row * N + col) = hv;
                    *(__half2*)(Cl + (size_t)row * N + col) = lv;
                } else {
                    *(float2*)(C + (size_t)row * N + col) = make_float2(v0, v1);
                }
            }
        }
    }
}

// ---------------- fp32 -> fp16 convert (weights: B operand, hi only) ----------------
__global__ __launch_bounds__(256) void k_cvt16(
    const float* __restrict__ s, __half* __restrict__ d, int n)
{
    const int i = blockIdx.x * 256 + threadIdx.x;
    if (i < n) d[i] = __float2half_rn(s[i]);
}

// ---------------- scalar fp32 SGEMM, reg-prefetch pipelined (QKV) ----------------
__global__ __launch_bounds__(256) void k_sgemm(
    const float* __restrict__ A, const float* __restrict__ B,
    const float* __restrict__ bias, float* __restrict__ C,
    int M, int N, int K)
{
    __shared__ float As[16][128];
    __shared__ float Bs[16][128];
    const int bm = blockIdx.y * 128;
    const int bn = blockIdx.x * 128;
    const int t  = threadIdx.x;
    const int tx = t & 15, ty = t >> 4;

    float acc[8][8];
#pragma unroll
    for (int i = 0; i < 8; i++)
#pragma unroll
        for (int j = 0; j < 8; j++) acc[i][j] = 0.0f;

    const int arow = t >> 1, acol = (t & 1) * 8;
    const int brow = t >> 4, bcol = (t & 15) * 8;
    const float* Ap = A + (size_t)(bm + arow) * K + acol;
    const float* Bp = B + (size_t)brow * N + bn + bcol;

    float4 pa0 = *(const float4*)(Ap);
    float4 pa1 = *(const float4*)(Ap + 4);
    float4 pb0 = *(const float4*)(Bp);
    float4 pb1 = *(const float4*)(Bp + 4);

    for (int k0 = 0; k0 < K; k0 += 16) {
        As[acol + 0][arow] = pa0.x; As[acol + 1][arow] = pa0.y;
        As[acol + 2][arow] = pa0.z; As[acol + 3][arow] = pa0.w;
        As[acol + 4][arow] = pa1.x; As[acol + 5][arow] = pa1.y;
        As[acol + 6][arow] = pa1.z; As[acol + 7][arow] = pa1.w;
        *(float4*)&Bs[brow][bcol]     = pb0;
        *(float4*)&Bs[brow][bcol + 4] = pb1;
        __syncthreads();
        if (k0 + 16 < K) {
            pa0 = *(const float4*)(Ap + k0 + 16);
            pa1 = *(const float4*)(Ap + k0 + 20);
            pb0 = *(const float4*)(Bp + (size_t)(k0 + 16) * N);
            pb1 = *(const float4*)(Bp + (size_t)(k0 + 16) * N + 4);
        }
#pragma unroll
        for (int kk = 0; kk < 16; kk++) {
            float a[8], b[8];
            *(float4*)(a)     = *(float4*)&As[kk][ty * 8];
            *(float4*)(a + 4) = *(float4*)&As[kk][ty * 8 + 4];
            *(float4*)(b)     = *(float4*)&Bs[kk][tx * 8];
            *(float4*)(b + 4) = *(float4*)&Bs[kk][tx * 8 + 4];
#pragma unroll
            for (int i = 0; i < 8; i++)
#pragma unroll
                for (int j = 0; j < 8; j++) acc[i][j] += a[i] * b[j];
        }
        __syncthreads();
    }

#pragma unroll
    for (int i = 0; i < 8; i++) {
        const int row = bm + ty * 8 + i;
#pragma unroll
        for (int j = 0; j < 8; j++) {
            C[(size_t)row * N + bn + tx * 8 + j] = acc[i][j] + bias[bn + tx * 8 + j];
        }
    }
}

// ---------------- per-(b,h) ksum / vmean ----------------
__global__ __launch_bounds__(256) void k_kstats()
{
    const int bh = blockIdx.x, b = bh >> 3, h = bh & 7;
    const int t = threadIdx.x;
    const int d = t & 63, c = t >> 6;
    float ks = 0.f, vs = 0.f;
    for (int n = c * 512; n < (c + 1) * 512; n++) {
        const float* p = g_qkv + (size_t)(b * SEQ + n) * QKVC + CMODEL + h * DK + d;
        ks += p[0];
        vs += p[CMODEL];
    }
    __shared__ float sk[256], sv[256];
    sk[t] = ks; sv[t] = vs;
    __syncthreads();
    if (t < 64) {
        float a = sk[t] + sk[t + 64] + sk[t + 128] + sk[t + 192];
        float v = sv[t] + sv[t + 64] + sv[t + 128] + sv[t + 192];
        g_ksum[bh * DK + t]  = a;
        g_vmean[bh * DK + t] = v * (1.0f / SEQ);
    }
}

// ---------------- streamed QK^T row-max + M: Q preloaded, 64-deep K tiles ----------------
#define RM_SMEM ((2*64*128 + 128*17 + 64) * 4)
__global__ __launch_bounds__(256) void k_rowmax()
{
    extern __shared__ float rs_[];
    float (*Qs)[128] = (float (*)[128])rs_;
    float (*Ks)[128] = (float (*)[128])(rs_ + 64 * 128);
    float (*red)[17] = (float (*)[17])(rs_ + 2 * 64 * 128);
    float* ks = rs_ + 2 * 64 * 128 + 128 * 17;

    const int bh = blockIdx.y, b = bh >> 3, h = bh & 7;
    const int bm = blockIdx.x * 128;
    const int t = threadIdx.x;
    const int tx = t & 15, ty = t >> 4;
    const int arow = t >> 1, acol = (t & 1) * 4;

    const float* qbase = g_qkv + (size_t)(b * SEQ) * QKVC + h * DK;
    const float* kbase = qbase + CMODEL;

    if (t < 64) ks[t] = g_ksum[bh * DK + t];
#pragma unroll
    for (int k0 = 0; k0 < DK; k0 += 8) {
        float4 av = *(const float4*)(qbase + (size_t)(bm + arow) * QKVC + k0 + acol);
        Qs[k0 + acol + 0][arow] = av.x; Qs[k0 + acol + 1][arow] = av.y;
        Qs[k0 + acol + 2][arow] = av.z; Qs[k0 + acol + 3][arow] = av.w;
    }

    float lmax[8];
#pragma unroll
    for (int i = 0; i < 8; i++) lmax[i] = NEGINF;

    for (int m0 = 0; m0 < SEQ; m0 += 128) {
        __syncthreads();
#pragma unroll
        for (int k0 = 0; k0 < DK; k0 += 8) {
            float4 bv = *(const float4*)(kbase + (size_t)(m0 + arow) * QKVC + k0 + acol);
            Ks[k0 + acol + 0][arow] = bv.x; Ks[k0 + acol + 1][arow] = bv.y;
            Ks[k0 + acol + 2][arow] = bv.z; Ks[k0 + acol + 3][arow] = bv.w;
        }
        __syncthreads();

        float acc[8][8];
#pragma unroll
        for (int i = 0; i < 8; i++)
#pragma unroll
            for (int j = 0; j < 8; j++) acc[i][j] = 0.0f;

#pragma unroll 8
        for (int kk = 0; kk < DK; kk++) {
            float a[8], bb[8];
            *(float4*)(a)      = *(float4*)&Qs[kk][ty * 8];
            *(float4*)(a + 4)  = *(float4*)&Qs[kk][ty * 8 + 4];
            *(float4*)(bb)     = *(float4*)&Ks[kk][tx * 8];
            *(float4*)(bb + 4) = *(float4*)&Ks[kk][tx * 8 + 4];
#pragma unroll
            for (int i = 0; i < 8; i++)
#pragma unroll
                for (int j = 0; j < 8; j++) acc[i][j] += a[i] * bb[j];
        }
#pragma unroll
        for (int i = 0; i < 8; i++) {
            float mx = acc[i][0];
#pragma unroll
            for (int j = 1; j < 8; j++) mx = fmaxf(mx, acc[i][j]);
            lmax[i] = fmaxf(lmax[i], mx);
        }
    }

    __syncthreads();
#pragma unroll
    for (int i = 0; i < 8; i++) red[ty * 8 + i][tx] = lmax[i];
    __syncthreads();
    if (t < 128) {
        float mx = red[t][0];
#pragma unroll
        for (int j = 1; j < 16; j++) mx = fmaxf(mx, red[t][j]);
        float qd = 0.f;
        const float* qp = qbase + (size_t)(bm + t) * QKVC;
#pragma unroll 8
        for (int d = 0; d < 64; d++) qd += qp[d] * ks[d];
        g_rowmax[bh * SEQ + bm + t] = SCALE * mx;
        g_M[bh * SEQ + bm + t]      = SCALE * mx - SCALE * qd * (1.0f / SEQ);
    }
}

// ---------------- exact top-512 per (b,h): in-smem bitonic sort ----------------
__global__ __launch_bounds__(1024) void k_topk()
{
    const int bh = blockIdx.x;
    const int t = threadIdx.x;
    __shared__ float sv[2048];
    __shared__ int   si[2048];
    sv[t]        = g_M[bh * SEQ + t];        si[t]        = t;
    sv[t + 1024] = g_M[bh * SEQ + t + 1024]; si[t + 1024] = t + 1024;

    for (int k = 2; k <= 2048; k <<= 1) {
        for (int j = k >> 1; j > 0; j >>= 1) {
            __syncthreads();
#pragma unroll 1
            for (int e = t; e < 2048; e += 1024) {
                const int p = e ^ j;
                if (p > e) {
                    float va = sv[e], vb = sv[p];
                    int   ia = si[e], ib = si[p];
                    bool gtr = (va > vb) || (va == vb && ia < ib);
                    bool desc = ((e & k) == 0);
                    if (desc ? !gtr : gtr) {
                        sv[e] = vb; sv[p] = va;
                        si[e] = ib; si[p] = ia;
                    }
                }
            }
        }
    }
    __syncthreads();
    if (t < NTOP) g_topidx[bh * NTOP + t] = si[t];
}

// ---------------- fill all rows with split(vmean) ----------------
__global__ __launch_bounds__(256) void k_fillsplit()
{
    const int i = blockIdx.x * 256 + threadIdx.x;
    const int c = i & 511;
    const int tok = i >> 9;
    const int b = tok >> 11;
    float v = g_vmean[(b * NHEADS + (c >> 6)) * DK + (c & 63)];
    __half h, l;
    split16(v, h, l);
    g_ah[i] = h; g_al[i] = l;
}

// ---------------- softmax @ V for selected rows: 32 rows/block, 256 thr ----------------
__global__ __launch_bounds__(256) void k_attn_sel()
{
    const int bh = blockIdx.y, b = bh >> 3, h = bh & 7;
    const int t = threadIdx.x;

    __shared__ float Qs[32][65];
    __shared__ float Ks[32][65];
    __shared__ float Vs[32][65];
    __shared__ float Se[32][33];
    __shared__ float sume[32];
    __shared__ float rmax[32];
    __shared__ int   nidx[32];

    if (t < 32) {
        int n = g_topidx[bh * NTOP + blockIdx.x * 32 + t];
        nidx[t] = n;
        sume[t] = 0.f;
        rmax[t] = g_rowmax[bh * SEQ + n];
    }
    __syncthreads();

#pragma unroll
    for (int i = 0; i < 2; i++) {
        const int idx = i * 256 + t;
        const int qr = idx >> 4, cc = (idx & 15) * 4;
        const float* qp = g_qkv + (size_t)(b * SEQ + nidx[qr]) * QKVC + h * DK + cc;
        float4 v = *(const float4*)qp;
        Qs[qr][cc + 0] = v.x; Qs[qr][cc + 1] = v.y;
        Qs[qr][cc + 2] = v.z; Qs[qr][cc + 3] = v.w;
    }

    const int r  = t >> 3;
    const int mg = (t & 7) * 4;
    const int dg = (t & 7) * 8;
    const float rm = rmax[r];

    float o[8];
#pragma unroll
    for (int i = 0; i < 8; i++) o[i] = 0.f;

    for (int m0 = 0; m0 < SEQ; m0 += 32) {
        __syncthreads();
#pragma unroll
        for (int i = 0; i < 2; i++) {
            const int idx = i * 256 + t;
            const int mr = idx >> 4, cc = (idx & 15) * 4;
            const float* kp = g_qkv + (size_t)(b * SEQ + m0 + mr) * QKVC + CMODEL + h * DK + cc;
            float4 kv = *(const float4*)kp;
            float4 vv = *(const float4*)(kp + CMODEL);
            Ks[mr][cc + 0] = kv.x; Ks[mr][cc + 1] = kv.y;
            Ks[mr][cc + 2] = kv.z; Ks[mr][cc + 3] = kv.w;
            Vs[mr][cc + 0] = vv.x; Vs[mr][cc + 1] = vv.y;
            Vs[mr][cc + 2] = vv.z; Vs[mr][cc + 3] = vv.w;
        }
        __syncthreads();

        float s[4];
#pragma unroll
        for (int j = 0; j < 4; j++) s[j] = 0.f;
#pragma unroll 8
        for (int d = 0; d < 64; d++) {
            const float qv = Qs[r][d];
#pragma unroll
            for (int j = 0; j < 4; j++) s[j] += qv * Ks[mg + j][d];
        }
        float lsum = 0.f;
#pragma unroll
        for (int j = 0; j < 4; j++) {
            float ev = __expf(s[j] * SCALE - rm);
            Se[r][mg + j] = ev;
            lsum += ev;
        }
        atomicAdd(&sume[r], lsum);
        __syncthreads();

#pragma unroll 8
        for (int m = 0; m < 32; m++) {
            const float ev = Se[r][m];
#pragma unroll
            for (int i = 0; i < 8; i++) o[i] += ev * Vs[m][dg + i];
        }
    }
    __syncthreads();
    const float inv = 1.0f / sume[r];
    const size_t base = (size_t)(b * SEQ + nidx[r]) * CMODEL + h * DK + dg;
#pragma unroll
    for (int i = 0; i < 8; i++) {
        __half hh, ll;
        split16(o[i] * inv, hh, ll);
        g_ah[base + i] = hh;
        g_al[base + i] = ll;
    }
}

// ---------------- fused residual add + LayerNorm (+ optional split output) ----------------
__global__ __launch_bounds__(128) void k_addln(
    const float* __restrict__ A, const float* __restrict__ Bv,
    const float* __restrict__ g, const float* __restrict__ be, float* __restrict__ O,
    __half* __restrict__ Oh, __half* __restrict__ Ol)
{
    const int row = blockIdx.x, t = threadIdx.x;
    float4 a = ((const float4*)(A  + (size_t)row * CMODEL))[t];
    float4 b = ((const float4*)(Bv + (size_t)row * CMODEL))[t];
    float v0 = a.x + b.x, v1 = a.y + b.y, v2 = a.z + b.z, v3 = a.w + b.w;

    __shared__ float ws[4];
    float s = v0 + v1 + v2 + v3;
#pragma unroll
    for (int o = 16; o > 0; o >>= 1) s += __shfl_xor_sync(0xffffffffu, s, o);
    if ((t & 31) == 0) ws[t >> 5] = s;
    __syncthreads();
    const float mean = (ws[0] + ws[1] + ws[2] + ws[3]) * (1.0f / CMODEL);
    v0 -= mean; v1 -= mean; v2 -= mean; v3 -= mean;
    float q = v0 * v0 + v1 * v1 + v2 * v2 + v3 * v3;
#pragma unroll
    for (int o = 16; o > 0; o >>= 1) q += __shfl_xor_sync(0xffffffffu, q, o);
    __syncthreads();
    if ((t & 31) == 0) ws[t >> 5] = q;
    __syncthreads();
    const float var = (ws[0] + ws[1] + ws[2] + ws[3]) * (1.0f / CMODEL);
    const float rs = rsqrtf(var + LNEPS);
    float4 gg = ((const float4*)g)[t], bb = ((const float4*)be)[t];
    float4 out;
    out.x = v0 * rs * gg.x + bb.x;
    out.y = v1 * rs * gg.y + bb.y;
    out.z = v2 * rs * gg.z + bb.z;
    out.w = v3 * rs * gg.w + bb.w;
    ((float4*)(O + (size_t)row * CMODEL))[t] = out;
    if (Oh) {
        const size_t base = (size_t)row * CMODEL + t * 4;
        __half h0, l0, h1, l1, h2, l2, h3, l3;
        split16(out.x, h0, l0); split16(out.y, h1, l1);
        split16(out.z, h2, l2); split16(out.w, h3, l3);
        __half2 ha; ha.x = h0; ha.y = h1;
        __half2 hb; hb.x = h2; hb.y = h3;
        __half2 la; la.x = l0; la.y = l1;
        __half2 lb; lb.x = l2; lb.y = l3;
        *(__half2*)(Oh + base)     = ha;
        *(__half2*)(Oh + base + 2) = hb;
        *(__half2*)(Ol + base)     = la;
        *(__half2*)(Ol + base + 2) = lb;
    }
}

// ---------------- conv weight: pack + fp16 convert in one pass (B operand) ----------------
__global__ __launch_bounds__(256) void k_packWcvt(const float* __restrict__ w)
{
    const int i = blockIdx.x * 256 + threadIdx.x;   // over 1536*512
    const int co = i & 511;
    const int rr = i >> 9;
    const int ci = rr & 511;
    const int k  = rr >> 9;
    g_bh[i] = __float2half_rn(w[(co * CMODEL + ci) * 3 + k]);
}

// ---------------- circular-shift pack of x2 -> split fp16 A [4096,1536] ----------------
__global__ __launch_bounds__(256) void k_packXcvt()
{
    const int i = blockIdx.x * 256 + threadIdx.x;
    const int col = i % QKVC, tok = i / QKVC;
    const int b = tok >> 11, n = tok & 2047;
    const int k = col >> 9, ci = col & 511;
    const int ns = (n - 1 + k + SEQ) & (SEQ - 1);
    __half h, l;
    split16(g_x2[(size_t)(b * SEQ + ns) * CMODEL + ci], h, l);
    g_ah[i] = h; g_al[i] = l;
}

// ---------------- maxpool + ELU + LayerNorm -> final output ----------------
__global__ __launch_bounds__(128) void k_poolln(
    const float* __restrict__ Y, const float* __restrict__ g,
    const float* __restrict__ be, float* __restrict__ O)
{
    const int row = blockIdx.x;
    const int b = row >> 10, j = row & 1023;
    const int t = threadIdx.x;
    const int c = t * 4;

    float m0 = NEGINF, m1 = NEGINF, m2 = NEGINF, m3 = NEGINF;
#pragma unroll
    for (int dn = 0; dn < 3; dn++) {
        const int n = 2 * j - 1 + dn;
        if (n >= 0 && n < SEQ) {
            float4 w = *(const float4*)(Y + (size_t)(b * SEQ + n) * CMODEL + c);
            m0 = fmaxf(m0, w.x); m1 = fmaxf(m1, w.y);
            m2 = fmaxf(m2, w.z); m3 = fmaxf(m3, w.w);
        }
    }
    float v0 = m0 > 0.f ? m0 : expm1f(m0);
    float v1 = m1 > 0.f ? m1 : expm1f(m1);
    float v2 = m2 > 0.f ? m2 : expm1f(m2);
    float v3 = m3 > 0.f ? m3 : expm1f(m3);

    __shared__ float ws[4];
    float s = v0 + v1 + v2 + v3;
#pragma unroll
    for (int o = 16; o > 0; o >>= 1) s += __shfl_xor_sync(0xffffffffu, s, o);
    if ((t & 31) == 0) ws[t >> 5] = s;
    __syncthreads();
    const float mean = (ws[0] + ws[1] + ws[2] + ws[3]) * (1.0f / CMODEL);
    v0 -= mean; v1 -= mean; v2 -= mean; v3 -= mean;
    float q = v0 * v0 + v1 * v1 + v2 * v2 + v3 * v3;
#pragma unroll
    for (int o = 16; o > 0; o >>= 1) q += __shfl_xor_sync(0xffffffffu, q, o);
    __syncthreads();
    if ((t & 31) == 0) ws[t >> 5] = q;
    __syncthreads();
    const float var = (ws[0] + ws[1] + ws[2] + ws[3]) * (1.0f / CMODEL);
    const float rs = rsqrtf(var + LNEPS);
    float4 gg = ((const float4*)g)[t], bb = ((const float4*)be)[t];
    float4 out;
    out.x = v0 * rs * gg.x + bb.x;
    out.y = v1 * rs * gg.y + bb.y;
    out.z = v2 * rs * gg.z + bb.z;
    out.w = v3 * rs * gg.w + bb.w;
    ((float4*)(O + (size_t)row * CMODEL))[t] = out;
}

// ---------------- host orchestration ----------------
extern "C" void kernel_launch(void* const* d_in, const int* in_sizes, int n_in,
                              void* d_out, int out_size)
{
    (void)in_sizes; (void)n_in; (void)out_size;
    const float* x      = (const float*)d_in[0];
    const float* qkv_w  = (const float*)d_in[1];
    const float* qkv_b  = (const float*)d_in[2];
    const float* out_w  = (const float*)d_in[3];
    const float* out_b  = (const float*)d_in[4];
    const float* ffn_w1 = (const float*)d_in[5];
    const float* ffn_b1 = (const float*)d_in[6];
    const float* ffn_w2 = (const float*)d_in[7];
    const float* ffn_b2 = (const float*)d_in[8];
    const float* n1_g   = (const float*)d_in[9];
    const float* n1_b   = (const float*)d_in[10];
    const float* n2_g   = (const float*)d_in[11];
    const float* n2_b   = (const float*)d_in[12];
    const float* conv_w = (const float*)d_in[13];
    const float* conv_b = (const float*)d_in[14];
    const float* cn_g   = (const float*)d_in[15];
    const float* cn_b   = (const float*)d_in[16];
    float* out = (float*)d_out;

    float *p_qkv, *p_t1, *p_x1, *p_x2, *p_cy;
    __half *p_ah, *p_al, *p_a2h, *p_a2l, *p_bh;
    cudaGetSymbolAddress((void**)&p_qkv,  g_qkv);
    cudaGetSymbolAddress((void**)&p_t1,   g_t1);
    cudaGetSymbolAddress((void**)&p_x1,   g_x1);
    cudaGetSymbolAddress((void**)&p_x2,   g_x2);
    cudaGetSymbolAddress((void**)&p_cy,   g_cy);
    cudaGetSymbolAddress((void**)&p_ah,   g_ah);
    cudaGetSymbolAddress((void**)&p_al,   g_al);
    cudaGetSymbolAddress((void**)&p_a2h,  g_a2h);
    cudaGetSymbolAddress((void**)&p_a2l,  g_a2l);
    cudaGetSymbolAddress((void**)&p_bh,   g_bh);

    cudaFuncSetAttribute(k_hgemm,  cudaFuncAttributeMaxDynamicSharedMemorySize, HG_SMEM);
    cudaFuncSetAttribute(k_rowmax, cudaFuncAttributeMaxDynamicSharedMemorySize, RM_SMEM);

    // 1) QKV projection (pipelined scalar fp32 — selection-critical)
    k_sgemm<<<dim3(QKVC / 128, NTOK / 128), 256>>>(x, qkv_w, qkv_b, p_qkv, NTOK, QKVC, CMODEL);
    // 2) stats, rowmax, top-k, attention (attn writes split attnO directly)
    k_kstats<<<BATCH * NHEADS, 256>>>();
    k_rowmax<<<dim3(SEQ / 128, BATCH * NHEADS), 256, RM_SMEM>>>();
    k_topk<<<BATCH * NHEADS, 1024>>>();
    k_fillsplit<<<(NTOK * CMODEL) / 256, 256>>>();
    k_attn_sel<<<dim3(NTOP / 32, BATCH * NHEADS), 256>>>();
    // 3) output projection + LN1 (LN1 emits x1 fp32 + fp16 splits)
    k_cvt16<<<(CMODEL * CMODEL) / 256, 256>>>(out_w, p_bh, CMODEL * CMODEL);
    k_hgemm<<<dim3(CMODEL / 128, NTOK / 128), 256, HG_SMEM>>>(p_ah, p_al, p_bh, out_b, p_t1, 0, 0, NTOK, CMODEL, CMODEL, 0, 0);
    k_addln<<<NTOK, 128>>>(x, p_t1, n1_g, n1_b, p_x1, p_ah, p_al);
    // 4) FFN (FFN1 emits split GELU output straight into FFN2's A operand) + LN2
    k_cvt16<<<(CMODEL * DFF) / 256, 256>>>(ffn_w1, p_bh, CMODEL * DFF);
    k_hgemm<<<dim3(DFF / 128, NTOK / 128), 256, HG_SMEM>>>(p_ah, p_al, p_bh, ffn_b1, 0, p_a2h, p_a2l, NTOK, DFF, CMODEL, 1, 1);
    k_cvt16<<<(DFF * CMODEL) / 256, 256>>>(ffn_w2, p_bh, DFF * CMODEL);
    k_hgemm<<<dim3(CMODEL / 128, NTOK / 128), 256, HG_SMEM>>>(p_a2h, p_a2l, p_bh, ffn_b2, p_t1, 0, 0, NTOK, CMODEL, DFF, 0, 0);
    k_addln<<<NTOK, 128>>>(p_x1, p_t1, n2_g, n2_b, p_x2, 0, 0);
    // 5) circular conv1d(k=3) as 2-term fp16 GEMM
    k_packWcvt<<<(QKVC * CMODEL) / 256, 256>>>(conv_w);
    k_packXcvt<<<(NTOK * QKVC) / 256, 256>>>();
    k_hgemm<<<dim3(CMODEL / 128, NTOK / 128), 256, HG_SMEM>>>(p_ah, p_al, p_bh, conv_b, p_cy, 0, 0, NTOK, CMODEL, QKVC, 0, 0);
    // 6) maxpool + ELU + LN -> d_out
    k_poolln<<<BATCH * (SEQ / 2), 128>>>(p_cy, cn_g, cn_b, out);
}